// round 7
// baseline (speedup 1.0000x reference)
#include <cuda_runtime.h>
#include <math.h>

constexpr int B_ = 2, C_ = 64, Hh = 48, Ww = 48, L_ = 2304;
constexpr int NH_ = 8, DK_ = 64, DV_ = 128;
constexpr int DN_ = 128, NS_ = 16, CM_ = 256;

// ---------------- scratch ---------------------------------------------------
__device__ float g_q[B_*NH_*L_*DK_];
__device__ float g_k[B_*NH_*L_*DK_];
__device__ float g_v[B_*NH_*L_*DV_];
__device__ float g_snrlog[B_*L_];
__device__ float g_attno[B_*L_*NH_*DV_];
__device__ float g_enc[B_*L_*C_];
__device__ float g_z[B_*L_*DN_];
__device__ float g_x1[B_*DN_*L_];
__device__ float g_x1c[B_*DN_*L_];
__device__ float g_dts[B_*4*L_*DN_];
__device__ float g_Bs[B_*4*L_*NS_];
__device__ float g_Cs[B_*4*L_*NS_];
__device__ float g_ys[B_*4*L_*DN_];
__device__ float g_x2[B_*L_*C_];
__device__ float g_xn[B_*L_*C_];
__device__ float g_h1[B_*CM_*L_];
__device__ float g_h2[B_*CM_*L_];

__device__ __forceinline__ float warp_sum(float v) {
  #pragma unroll
  for (int o = 16; o > 0; o >>= 1) v += __shfl_xor_sync(0xffffffffu, v, o);
  return v;
}

__device__ __forceinline__ float gelu_exact(float x) {
  return 0.5f * x * (1.0f + erff(x * 0.70710678118654752f));
}

__device__ __forceinline__ unsigned f2r(float x) { return __float_as_uint(x); }

__device__ __forceinline__ void mma_tf32(float* d, const unsigned* a, unsigned b0, unsigned b1) {
  asm volatile("mma.sync.aligned.m16n8k8.row.col.f32.tf32.tf32.f32 "
    "{%0,%1,%2,%3}, {%4,%5,%6,%7}, {%8,%9}, {%0,%1,%2,%3};"
    : "+f"(d[0]), "+f"(d[1]), "+f"(d[2]), "+f"(d[3])
    : "r"(a[0]), "r"(a[1]), "r"(a[2]), "r"(a[3]), "r"(b0), "r"(b1));
}

__device__ __forceinline__ void cp16(unsigned s, const void* g) {
  asm volatile("cp.async.cg.shared.global [%0], [%1], 16;" :: "r"(s), "l"(g));
}

// ---------------- K0 --------------------------------------------------------
__global__ void k_snr(const float* __restrict__ snr) {
  int i = blockIdx.x*512 + threadIdx.x;
  if (i < B_*L_) g_snrlog[i] = logf(snr[i] + 1e-4f);
}

// ---------------- K1: QKV projection, 16 tokens/block ----------------------
// grid 288, block 512: half = token-subset, both halves share weight lines (L1)
__global__ void __launch_bounds__(512) k_qkv(const float* __restrict__ x,
                      const float* __restrict__ wq,
                      const float* __restrict__ wk,
                      const float* __restrict__ wv) {
  __shared__ float sx[16][64];
  int blk = blockIdx.x;
  int b = blk / 144;
  int t0 = (blk % 144) * 16;
  int tid = threadIdx.x;
  for (int i = tid; i < 1024; i += 512) {
    int cc = i >> 4, tt = i & 15;
    sx[tt][cc] = x[(b*C_ + cc)*L_ + t0 + tt];
  }
  __syncthreads();
  int half = tid >> 8;              // token half: 0 -> tokens 0-7, 1 -> 8-15
  int tb = half * 8;
  int c0 = (tid & 255) * 8;
  const float* wp;
  int stride;
  if (c0 < 512)       { wp = wq + c0;          stride = 512; }
  else if (c0 < 1024) { wp = wk + (c0 - 512);  stride = 512; }
  else                { wp = wv + (c0 - 1024); stride = 1024; }
  float acc[8][8];
  #pragma unroll
  for (int i = 0; i < 8; i++)
    #pragma unroll
    for (int j = 0; j < 8; j++) acc[i][j] = 0.f;
  for (int cc = 0; cc < 64; cc++) {
    float4 w0 = *(const float4*)&wp[cc*stride];
    float4 w1 = *(const float4*)&wp[cc*stride + 4];
    float w[8] = {w0.x, w0.y, w0.z, w0.w, w1.x, w1.y, w1.z, w1.w};
    #pragma unroll
    for (int tt = 0; tt < 8; tt++) {
      float xv = sx[tb + tt][cc];
      #pragma unroll
      for (int j = 0; j < 8; j++) acc[tt][j] = fmaf(xv, w[j], acc[tt][j]);
    }
  }
  #pragma unroll
  for (int tt = 0; tt < 8; tt++) {
    int l = t0 + tb + tt;
    float4 lo = {acc[tt][0], acc[tt][1], acc[tt][2], acc[tt][3]};
    float4 hi = {acc[tt][4], acc[tt][5], acc[tt][6], acc[tt][7]};
    if (c0 < 512) {
      int h = c0 >> 6, d = c0 & 63;
      float* p = &g_q[((b*NH_ + h)*L_ + l)*DK_ + d];
      *(float4*)p = lo; *(float4*)(p + 4) = hi;
    } else if (c0 < 1024) {
      int c2 = c0 - 512; int h = c2 >> 6, d = c2 & 63;
      float* p = &g_k[((b*NH_ + h)*L_ + l)*DK_ + d];
      *(float4*)p = lo; *(float4*)(p + 4) = hi;
    } else {
      int c2 = c0 - 1024; int h = c2 >> 7, d = c2 & 127;
      float* p = &g_v[((b*NH_ + h)*L_ + l)*DV_ + d];
      *(float4*)p = lo; *(float4*)(p + 4) = hi;
    }
  }
}

// ---------------- K2: flash attention, tf32 mma ----------------------------
constexpr int KSTR = 68;
constexpr int VSTR = 136;
constexpr int KTILE = 64*KSTR;
constexpr int VTILE = 64*VSTR;

__global__ void __launch_bounds__(256, 1) k_attn() {
  extern __shared__ float sm[];
  float* sKb[2] = { sm, sm + KTILE };
  float* sVb[2] = { sm + 2*KTILE, sm + 2*KTILE + VTILE };

  int tid = threadIdx.x;
  int wid = tid >> 5, lane = tid & 31;
  int g = lane >> 2, t = lane & 3;
  int bh = blockIdx.y;
  int b = bh >> 3, h = bh & 7;
  int q0 = blockIdx.x * 128;
  int m0 = wid * 16;

  unsigned smbase = (unsigned)__cvta_generic_to_shared(sm);

  unsigned qf[8][4];
  {
    const float* qp0 = g_q + ((size_t)bh*L_ + q0 + m0 + g)*64;
    const float* qp1 = qp0 + 8*64;
    #pragma unroll
    for (int ks = 0; ks < 8; ks++) {
      qf[ks][0] = f2r(qp0[8*ks + t]);
      qf[ks][1] = f2r(qp1[8*ks + t]);
      qf[ks][2] = f2r(qp0[8*ks + t + 4]);
      qf[ks][3] = f2r(qp1[8*ks + t + 4]);
    }
  }

  float oacc[16][4];
  #pragma unroll
  for (int j = 0; j < 16; j++)
    #pragma unroll
    for (int r = 0; r < 4; r++) oacc[j][r] = 0.f;
  float mrun0 = -1e30f, mrun1 = -1e30f, l0 = 0.f, l1 = 0.f;

  const float* snrl = g_snrlog + b*L_;

  {
    const float* kp = g_k + ((size_t)bh*L_)*64;
    const float* vp = g_v + ((size_t)bh*L_)*128;
    unsigned kS = smbase;
    unsigned vS = smbase + 2*KTILE*4;
    #pragma unroll
    for (int i = 0; i < 4; i++) {
      int idx = tid + 256*i; int row = idx >> 4, ch = idx & 15;
      cp16(kS + (row*KSTR + ch*4)*4, kp + row*64 + ch*4);
    }
    #pragma unroll
    for (int i = 0; i < 8; i++) {
      int idx = tid + 256*i; int row = idx >> 5, ch = idx & 31;
      cp16(vS + (row*VSTR + ch*4)*4, vp + row*128 + ch*4);
    }
  }
  asm volatile("cp.async.commit_group;");

  int stage = 0;
  for (int kt = 0; kt < 36; kt++) {
    if (kt + 1 < 36) {
      int kv1 = (kt + 1) * 64;
      const float* kp = g_k + ((size_t)bh*L_ + kv1)*64;
      const float* vp = g_v + ((size_t)bh*L_ + kv1)*128;
      int st = stage ^ 1;
      unsigned kS = smbase + (unsigned)(st*KTILE)*4;
      unsigned vS = smbase + (unsigned)(2*KTILE + st*VTILE)*4;
      #pragma unroll
      for (int i = 0; i < 4; i++) {
        int idx = tid + 256*i; int row = idx >> 4, ch = idx & 15;
        cp16(kS + (row*KSTR + ch*4)*4, kp + row*64 + ch*4);
      }
      #pragma unroll
      for (int i = 0; i < 8; i++) {
        int idx = tid + 256*i; int row = idx >> 5, ch = idx & 31;
        cp16(vS + (row*VSTR + ch*4)*4, vp + row*128 + ch*4);
      }
    }
    asm volatile("cp.async.commit_group;");
    asm volatile("cp.async.wait_group 1;");
    __syncthreads();

    const float* sK = sKb[stage];
    const float* sV = sVb[stage];
    int kv0 = kt * 64;

    float sacc[8][4];
    #pragma unroll
    for (int j = 0; j < 8; j++)
      #pragma unroll
      for (int r = 0; r < 4; r++) sacc[j][r] = 0.f;
    #pragma unroll
    for (int ks = 0; ks < 8; ks++) {
      #pragma unroll
      for (int j = 0; j < 8; j++) {
        unsigned b0 = f2r(sK[(8*j + g)*KSTR + 8*ks + t]);
        unsigned b1 = f2r(sK[(8*j + g)*KSTR + 8*ks + t + 4]);
        mma_tf32(sacc[j], qf[ks], b0, b1);
      }
    }

    #pragma unroll
    for (int j = 0; j < 8; j++) {
      float2 sb = *(const float2*)&snrl[kv0 + 8*j + 2*t];
      sacc[j][0] = sacc[j][0]*0.125f + sb.x;
      sacc[j][1] = sacc[j][1]*0.125f + sb.y;
      sacc[j][2] = sacc[j][2]*0.125f + sb.x;
      sacc[j][3] = sacc[j][3]*0.125f + sb.y;
    }

    float m0l = -1e30f, m1l = -1e30f;
    #pragma unroll
    for (int j = 0; j < 8; j++) {
      m0l = fmaxf(m0l, fmaxf(sacc[j][0], sacc[j][1]));
      m1l = fmaxf(m1l, fmaxf(sacc[j][2], sacc[j][3]));
    }
    m0l = fmaxf(m0l, __shfl_xor_sync(0xffffffffu, m0l, 1));
    m0l = fmaxf(m0l, __shfl_xor_sync(0xffffffffu, m0l, 2));
    m1l = fmaxf(m1l, __shfl_xor_sync(0xffffffffu, m1l, 1));
    m1l = fmaxf(m1l, __shfl_xor_sync(0xffffffffu, m1l, 2));
    float m0n = fmaxf(mrun0, m0l), m1n = fmaxf(mrun1, m1l);
    float sc0 = __expf(mrun0 - m0n), sc1 = __expf(mrun1 - m1n);
    float s0 = 0.f, s1 = 0.f;
    #pragma unroll
    for (int j = 0; j < 8; j++) {
      float p0 = __expf(sacc[j][0] - m0n);
      float p1 = __expf(sacc[j][1] - m0n);
      float p2 = __expf(sacc[j][2] - m1n);
      float p3 = __expf(sacc[j][3] - m1n);
      sacc[j][0] = p0; sacc[j][1] = p1; sacc[j][2] = p2; sacc[j][3] = p3;
      s0 += p0 + p1; s1 += p2 + p3;
    }
    s0 += __shfl_xor_sync(0xffffffffu, s0, 1);
    s0 += __shfl_xor_sync(0xffffffffu, s0, 2);
    s1 += __shfl_xor_sync(0xffffffffu, s1, 1);
    s1 += __shfl_xor_sync(0xffffffffu, s1, 2);
    l0 = l0*sc0 + s0; l1 = l1*sc1 + s1;
    mrun0 = m0n; mrun1 = m1n;
    #pragma unroll
    for (int j = 0; j < 16; j++) {
      oacc[j][0] *= sc0; oacc[j][1] *= sc0;
      oacc[j][2] *= sc1; oacc[j][3] *= sc1;
    }

    int srcA = (lane & 28) | (t >> 1);
    int srcB = srcA + 2;
    bool odd = (t & 1);
    #pragma unroll
    for (int ks = 0; ks < 8; ks++) {
      float c0 = sacc[ks][0], c1 = sacc[ks][1], c2 = sacc[ks][2], c3 = sacc[ks][3];
      float r0 = __shfl_sync(0xffffffffu, c0, srcA);
      float r1 = __shfl_sync(0xffffffffu, c1, srcA);
      float r2 = __shfl_sync(0xffffffffu, c0, srcB);
      float r3 = __shfl_sync(0xffffffffu, c1, srcB);
      float r4 = __shfl_sync(0xffffffffu, c2, srcA);
      float r5 = __shfl_sync(0xffffffffu, c3, srcA);
      float r6 = __shfl_sync(0xffffffffu, c2, srcB);
      float r7 = __shfl_sync(0xffffffffu, c3, srcB);
      unsigned pa[4];
      pa[0] = f2r(odd ? r1 : r0);
      pa[1] = f2r(odd ? r5 : r4);
      pa[2] = f2r(odd ? r3 : r2);
      pa[3] = f2r(odd ? r7 : r6);
      const float* v0 = sV + (8*ks + t)*VSTR + g;
      const float* v1 = sV + (8*ks + t + 4)*VSTR + g;
      #pragma unroll
      for (int j2 = 0; j2 < 16; j2++) {
        unsigned b0 = f2r(v0[8*j2]);
        unsigned b1 = f2r(v1[8*j2]);
        mma_tf32(oacc[j2], pa, b0, b1);
      }
    }
    stage ^= 1;
    __syncthreads();
  }

  float inv0 = 1.f / l0, inv1 = 1.f / l1;
  int row0 = q0 + m0 + g;
  float* op0 = g_attno + ((size_t)(b*L_ + row0))*1024 + h*128;
  float* op1 = op0 + (size_t)8*1024;
  #pragma unroll
  for (int j2 = 0; j2 < 16; j2++) {
    float2 v0 = { oacc[j2][0]*inv0, oacc[j2][1]*inv0 };
    float2 v1 = { oacc[j2][2]*inv1, oacc[j2][3]*inv1 };
    *(float2*)&op0[8*j2 + 2*t] = v0;
    *(float2*)&op1[8*j2 + 2*t] = v1;
  }
}

// ---------------- K3: attn out proj + residual + LN (tiled GEMM, 8 warps) --
// grid 144 (32 tokens/block), block 256. thread tile: 2 tokens x 4 channels
__global__ void __launch_bounds__(256) k_attn_epi(const float* __restrict__ x,
                           const float* __restrict__ fc,
                           const float* __restrict__ lnw,
                           const float* __restrict__ lnb) {
  __shared__ float sA[64*33];
  __shared__ float sB[64*68];
  __shared__ float sout[32][64];
  int blk = blockIdx.x;
  int b = blk / 72;
  int t0 = (blk % 72) * 32;
  int tid = threadIdx.x;
  int cg = tid & 15, tg = tid >> 4;     // tg 0..15, 2 tokens each
  float acc[2][4];
  #pragma unroll
  for (int u = 0; u < 2; u++)
    #pragma unroll
    for (int r = 0; r < 4; r++) acc[u][r] = 0.f;

  for (int kc = 0; kc < 16; kc++) {
    __syncthreads();
    for (int i = tid; i < 2048; i += 256) {
      int tok = i >> 6, kk = i & 63;
      sA[kk*33 + tok] = g_attno[((size_t)(b*L_ + t0 + tok))*1024 + kc*64 + kk];
    }
    for (int i = tid*4; i < 4096; i += 1024) {
      int kk = i >> 6, c = i & 63;
      *(float4*)&sB[kk*68 + c] = *(const float4*)&fc[(size_t)(kc*64 + kk)*64 + c];
    }
    __syncthreads();
    #pragma unroll 4
    for (int kk = 0; kk < 64; kk++) {
      float4 w = *(const float4*)&sB[kk*68 + cg*4];
      float x0 = sA[kk*33 + tg*2];
      float x1 = sA[kk*33 + tg*2 + 1];
      acc[0][0] = fmaf(x0, w.x, acc[0][0]); acc[0][1] = fmaf(x0, w.y, acc[0][1]);
      acc[0][2] = fmaf(x0, w.z, acc[0][2]); acc[0][3] = fmaf(x0, w.w, acc[0][3]);
      acc[1][0] = fmaf(x1, w.x, acc[1][0]); acc[1][1] = fmaf(x1, w.y, acc[1][1]);
      acc[1][2] = fmaf(x1, w.z, acc[1][2]); acc[1][3] = fmaf(x1, w.w, acc[1][3]);
    }
  }
  #pragma unroll
  for (int u = 0; u < 2; u++) {
    int tok = tg*2 + u;
    #pragma unroll
    for (int r = 0; r < 4; r++) {
      int c = cg*4 + r;
      sout[tok][c] = acc[u][r] + x[(b*C_ + c)*L_ + t0 + tok];
    }
  }
  __syncthreads();
  int lane = tid & 31, wid = tid >> 5;
  for (int tok = wid; tok < 32; tok += 8) {
    float v0 = sout[tok][lane], v1 = sout[tok][lane + 32];
    float mean = warp_sum(v0 + v1) * (1.f/64.f);
    float d0 = v0 - mean, d1 = v1 - mean;
    float var = warp_sum(d0*d0 + d1*d1) * (1.f/64.f);
    float rs = rsqrtf(var + 1e-5f);
    int l = t0 + tok;
    g_enc[(b*L_ + l)*64 + lane]      = d0*rs*lnw[lane] + lnb[lane];
    g_enc[(b*L_ + l)*64 + lane + 32] = d1*rs*lnw[lane + 32] + lnb[lane + 32];
  }
}

// ---------------- K4: SS input projection, 32 tokens/block -----------------
__global__ void __launch_bounds__(256) k_ssin(const float* __restrict__ w) {
  extern __shared__ float sw[];           // 64*256 floats
  __shared__ float sxe[32][64];
  int blk = blockIdx.x;
  int b = blk / 72;
  int t0 = (blk % 72) * 32;
  int tid = threadIdx.x;
  for (int i = tid*4; i < 16384; i += 1024)
    *(float4*)&sw[i] = *(const float4*)&w[i];
  for (int i = tid; i < 2048; i += 256)
    sxe[i>>6][i&63] = g_enc[(b*L_ + t0 + (i>>6))*64 + (i&63)];
  __syncthreads();
  int tok0 = (tid >> 4)*2, c0 = tid & 15;
  float acc[2][16];
  #pragma unroll
  for (int u = 0; u < 2; u++)
    #pragma unroll
    for (int j = 0; j < 16; j++) acc[u][j] = 0.f;
  for (int cc = 0; cc < 64; cc++) {
    float x0 = sxe[tok0][cc], x1 = sxe[tok0 + 1][cc];
    #pragma unroll
    for (int j = 0; j < 16; j++) {
      float wv = sw[cc*256 + c0 + 16*j];
      acc[0][j] = fmaf(x0, wv, acc[0][j]);
      acc[1][j] = fmaf(x1, wv, acc[1][j]);
    }
  }
  #pragma unroll
  for (int u = 0; u < 2; u++) {
    int l = t0 + tok0 + u;
    #pragma unroll
    for (int j = 0; j < 16; j++) {
      int c = c0 + 16*j;
      if (c < 128) g_x1[(b*128 + c)*L_ + l] = acc[u][j];
      else         g_z[(b*L_ + l)*128 + (c - 128)] = acc[u][j];
    }
  }
}

// ---------------- K5: depthwise conv3x3 + bias + silu ----------------------
__global__ void k_dw1(const float* __restrict__ w, const float* __restrict__ bias) {
  int p = blockIdx.x*256 + threadIdx.x;
  if (p >= B_*DN_*L_) return;
  int b = p / (DN_*L_);
  int rem = p - b*DN_*L_;
  int d = rem / L_;
  int hw = rem - d*L_;
  int i = hw / Ww, j = hw - i*Ww;
  const float* src = g_x1 + (b*DN_ + d)*L_;
  const float* wr = w + d*9;
  float acc = bias[d];
  #pragma unroll
  for (int kh = -1; kh <= 1; kh++) {
    int ih = i + kh;
    if (ih < 0 || ih >= Hh) continue;
    #pragma unroll
    for (int kw = -1; kw <= 1; kw++) {
      int iw = j + kw;
      if (iw < 0 || iw >= Ww) continue;
      acc = fmaf(src[ih*Ww + iw], wr[(kh+1)*3 + (kw+1)], acc);
    }
  }
  float s = acc / (1.f + __expf(-acc));
  g_x1c[(b*DN_ + d)*L_ + hw] = s;
}

__device__ __forceinline__ int xs_src(int k, int l) {
  if (k == 0) return l;
  int i = l / 48, j = l - i*48;
  if (k == 1) return j*48 + i;
  if (k == 2) return L_ - 1 - l;
  return (47 - j)*48 + (47 - i);
}

// ---------------- K6: x_dbl projection + dt proj + softplus, 32 tokens -----
__global__ void __launch_bounds__(256) k_xdbl(const float* __restrict__ xw,
                       const float* __restrict__ dtw,
                       const float* __restrict__ dtb) {
  __shared__ float sxs[32][130];
  __shared__ float sxw[128][37];
  __shared__ float sdt[32][4];
  __shared__ float sdtw[128][5];
  __shared__ float sdtbv[128];
  int t = blockIdx.x;
  int lt = t % 72;
  int k = (t / 72) & 3;
  int b = t / 288;
  int l0 = lt * 32;
  int tid = threadIdx.x;
  for (int i = tid; i < 4608; i += 256) {
    int c = i >> 7, d = i & 127;
    sxw[d][c] = xw[(size_t)k*4608 + i];
  }
  for (int i = tid; i < 512; i += 256) {
    int d = i >> 2, r = i & 3;
    sdtw[d][r] = dtw[(size_t)k*512 + i];
  }
  if (tid < 128) sdtbv[tid] = dtb[k*128 + tid];
  for (int i3 = tid; i3 < 4096; i3 += 256) {
    int tt = i3 >> 7, d = i3 & 127;
    int src = xs_src(k, l0 + tt);
    sxs[tt][d] = g_x1c[(b*128 + d)*L_ + src];
  }
  __syncthreads();
  for (int o = tid; o < 32*36; o += 256) {
    int ll = o / 36, c = o - ll*36;
    float acc = 0.f;
    #pragma unroll 4
    for (int d = 0; d < 128; d++) acc = fmaf(sxs[ll][d], sxw[d][c], acc);
    int l = l0 + ll;
    if (c < 4)       sdt[ll][c] = acc;
    else if (c < 20) g_Bs[((b*4 + k)*L_ + l)*16 + (c - 4)]  = acc;
    else             g_Cs[((b*4 + k)*L_ + l)*16 + (c - 20)] = acc;
  }
  __syncthreads();
  for (int o = tid; o < 32*128; o += 256) {
    int ll = o >> 7, d = o & 127;
    float acc = sdtbv[d];
    #pragma unroll
    for (int r = 0; r < 4; r++) acc = fmaf(sdt[ll][r], sdtw[d][r], acc);
    float sp = (acc > 20.f) ? acc : log1pf(__expf(acc));
    g_dts[((b*4 + k)*L_ + l0 + ll)*128 + d] = sp;
  }
}

// ---------------- K7: selective scan ---------------------------------------
__global__ void k_scan(const float* __restrict__ Alog, const float* __restrict__ Dw) {
  int gw = blockIdx.x;
  int lane = threadIdx.x;
  int b = gw >> 8;
  int rem = gw & 255;
  int k = rem >> 6;
  int dp = rem & 63;
  int n = lane & 15;
  int d = dp*2 + (lane >> 4);

  float An = -__expf(Alog[(k*128 + d)*16 + n]);
  float Dd = Dw[k*128 + d];
  const float* dtp = g_dts + ((size_t)(b*4 + k)*L_)*128 + d;
  const float* Bp  = g_Bs  + ((size_t)(b*4 + k)*L_)*16 + n;
  const float* Cp  = g_Cs  + ((size_t)(b*4 + k)*L_)*16 + n;
  float*       yp  = g_ys  + ((size_t)(b*4 + k)*L_)*128 + d;
  const float* xp  = g_x1c + (b*128 + d)*L_;

  float hst = 0.f;
  int ii = 0, jj = 0;
  for (int l0 = 0; l0 < L_; l0 += 8) {
    float dt[8], xv[8], Bn[8], Cn[8];
    #pragma unroll
    for (int u = 0; u < 8; u++) {
      int l = l0 + u;
      int src;
      if (k == 0)      src = l;
      else if (k == 1) src = jj*48 + ii;
      else if (k == 2) src = L_ - 1 - l;
      else             src = (47 - jj)*48 + (47 - ii);
      dt[u] = dtp[l*128];
      xv[u] = xp[src];
      Bn[u] = Bp[l*16];
      Cn[u] = Cp[l*16];
      jj++;
      if (jj == 48) { jj = 0; ii++; }
    }
    #pragma unroll
    for (int u = 0; u < 8; u++) {
      float dA = __expf(dt[u] * An);
      hst = fmaf(hst, dA, dt[u]*xv[u]*Bn[u]);
      float y = hst * Cn[u];
      y += __shfl_xor_sync(0xffffffffu, y, 1);
      y += __shfl_xor_sync(0xffffffffu, y, 2);
      y += __shfl_xor_sync(0xffffffffu, y, 4);
      y += __shfl_xor_sync(0xffffffffu, y, 8);
      if (n == 0) yp[(l0 + u)*128] = fmaf(Dd, xv[u], y);
    }
  }
}

// ---------------- K8: merge + LN + gate + out proj + LN (fused stats) ------
__global__ void __launch_bounds__(128) k_merge(const float* __restrict__ x,
                        const float* __restrict__ snr,
                        const float* __restrict__ nw, const float* __restrict__ nb,
                        const float* __restrict__ ow,
                        const float* __restrict__ flnw, const float* __restrict__ flnb) {
  __shared__ float sow[128*64];
  __shared__ float sy[128];
  __shared__ float red[4], red2[4];
  __shared__ float spart[2][64];
  int blk = blockIdx.x;
  int b = blk / 288;
  int t0 = (blk % 288) * 8;
  int tid = threadIdx.x, lane = tid & 31, wid = tid >> 5;
  for (int i = tid*4; i < 8192; i += 512)
    *(float4*)&sow[i] = *(const float4*)&ow[i];
  size_t base = (size_t)b*4*L_*128;
  float nwv = nw[tid], nbv = nb[tid];
  __syncthreads();

  for (int tok = 0; tok < 8; tok++) {
    int l = t0 + tok;
    int i = l / 48, j = l - i*48;
    int lt = j*48 + i;
    float y = g_ys[base + ((size_t)0*L_ + l)*128 + tid]
            + g_ys[base + ((size_t)2*L_ + (L_ - 1 - l))*128 + tid]
            + g_ys[base + ((size_t)1*L_ + lt)*128 + tid]
            + g_ys[base + ((size_t)3*L_ + (L_ - 1 - lt))*128 + tid];
    float s1 = warp_sum(y), s2 = warp_sum(y*y);
    if (lane == 0) { red[wid] = s1; red2[wid] = s2; }
    __syncthreads();
    float mean = (red[0] + red[1] + red[2] + red[3]) * (1.f/128.f);
    float var  = fmaxf((red2[0] + red2[1] + red2[2] + red2[3]) * (1.f/128.f) - mean*mean, 0.f);
    float yn = (y - mean) * rsqrtf(var + 1e-5f) * nwv + nbv;
    float z = g_z[(b*L_ + l)*128 + tid];
    float sz = z / (1.f + __expf(-z));
    float sv = snr[b*L_ + l];
    sy[tid] = yn * sz * sv;
    __syncthreads();
    {
      int c = tid & 63, half = tid >> 6;
      float acc = 0.f;
      int d0 = half*64;
      #pragma unroll 8
      for (int d = 0; d < 64; d++) acc = fmaf(sy[d0 + d], sow[(d0 + d)*64 + c], acc);
      spart[half][c] = acc;
    }
    __syncthreads();
    float v = 0.f;
    if (tid < 64) {
      v = spart[0][tid] + spart[1][tid] + x[(b*C_ + tid)*L_ + l];
      g_x2[(b*L_ + l)*64 + tid] = v;
    }
    float t1 = warp_sum(tid < 64 ? v : 0.f);
    float t2 = warp_sum(tid < 64 ? v*v : 0.f);
    if (lane == 0) { red[wid] = t1; red2[wid] = t2; }
    __syncthreads();
    float mean2 = (red[0] + red[1]) * (1.f/64.f);
    float var2  = fmaxf((red2[0] + red2[1]) * (1.f/64.f) - mean2*mean2, 0.f);
    if (tid < 64)
      g_xn[(b*L_ + l)*64 + tid] = (v - mean2) * rsqrtf(var2 + 1e-5f) * flnw[tid] + flnb[tid];
    __syncthreads();
  }
}

// ---------------- K9: FFN conv1x1 64->256 + gelu, 32 tokens ----------------
__global__ void __launch_bounds__(256) k_ffn1(const float* __restrict__ w1) {
  extern __shared__ float sw1[];          // [64][257]
  __shared__ float sx[32][64];
  int blk = blockIdx.x;
  int b = blk / 72;
  int t0 = (blk % 72) * 32;
  int tid = threadIdx.x;
  for (int i = tid; i < 16384; i += 256) {
    int oc = i >> 6, cc = i & 63;
    sw1[cc*257 + oc] = w1[i];
  }
  for (int i = tid; i < 2048; i += 256) {
    int tt = i >> 6, cc = i & 63;
    sx[tt][cc] = g_xn[(b*L_ + t0 + tt)*64 + cc];
  }
  __syncthreads();
  int oc = tid;
  float acc[32];
  #pragma unroll
  for (int q = 0; q < 32; q++) acc[q] = 0.f;
  for (int cc = 0; cc < 64; cc++) {
    float w = sw1[cc*257 + oc];
    #pragma unroll
    for (int q = 0; q < 32; q++) acc[q] = fmaf(sx[q][cc], w, acc[q]);
  }
  float* dst = g_h1 + (b*CM_ + oc)*L_ + t0;
  #pragma unroll
  for (int q = 0; q < 32; q++) dst[q] = gelu_exact(acc[q]);
}

// ---------------- K10: FFN depthwise conv3x3 + gelu ------------------------
__global__ void k_dw2(const float* __restrict__ w) {
  int p = blockIdx.x*256 + threadIdx.x;
  if (p >= B_*CM_*L_) return;
  int b = p / (CM_*L_);
  int rem = p - b*CM_*L_;
  int ch = rem / L_;
  int hw = rem - ch*L_;
  int i = hw / Ww, j = hw - i*Ww;
  const float* src = g_h1 + (b*CM_ + ch)*L_;
  const float* wr = w + ch*9;
  float acc = 0.f;
  #pragma unroll
  for (int kh = -1; kh <= 1; kh++) {
    int ih = i + kh;
    if (ih < 0 || ih >= Hh) continue;
    #pragma unroll
    for (int kw = -1; kw <= 1; kw++) {
      int iw = j + kw;
      if (iw < 0 || iw >= Ww) continue;
      acc = fmaf(src[ih*Ww + iw], wr[(kh+1)*3 + (kw+1)], acc);
    }
  }
  g_h2[(b*CM_ + ch)*L_ + hw] = gelu_exact(acc);
}

// ---------------- K11: FFN conv1x1 256->64 + residual, 32 tokens -----------
__global__ void __launch_bounds__(256) k_ffn2(const float* __restrict__ w2, float* __restrict__ out) {
  extern __shared__ float sw2[];          // [256][65]
  __shared__ float sh[256][32];
  int blk = blockIdx.x;
  int b = blk / 72;
  int t0 = (blk % 72) * 32;
  int tid = threadIdx.x;
  for (int i = tid; i < 16384; i += 256) {
    int c = i >> 8, oc = i & 255;
    sw2[oc*65 + c] = w2[i];
  }
  for (int i = tid; i < 8192; i += 256) {
    int oc = i >> 5, tt = i & 31;
    sh[oc][tt] = g_h2[(b*CM_ + oc)*L_ + t0 + tt];
  }
  __syncthreads();
  int c = tid & 63, tg = tid >> 6;      // 4 groups x 8 tokens
  float acc[8];
  #pragma unroll
  for (int q = 0; q < 8; q++) acc[q] = 0.f;
  for (int oc = 0; oc < 256; oc++) {
    float w = sw2[oc*65 + c];
    #pragma unroll
    for (int q = 0; q < 8; q++) acc[q] = fmaf(sh[oc][tg*8 + q], w, acc[q]);
  }
  #pragma unroll
  for (int q = 0; q < 8; q++) {
    int l = t0 + tg*8 + q;
    out[(b*C_ + c)*L_ + l] = acc[q] + g_x2[(b*L_ + l)*64 + c];
  }
}

// ---------------- launch ----------------------------------------------------
extern "C" void kernel_launch(void* const* d_in, const int* in_sizes, int n_in,
                              void* d_out, int out_size) {
  const float* enc     = (const float*)d_in[0];
  const float* snr     = (const float*)d_in[1];
  const float* wq      = (const float*)d_in[2];
  const float* wk      = (const float*)d_in[3];
  const float* wv      = (const float*)d_in[4];
  const float* fc      = (const float*)d_in[5];
  const float* aln_w   = (const float*)d_in[6];
  const float* aln_b   = (const float*)d_in[7];
  const float* ss_in_w = (const float*)d_in[8];
  const float* conv_w  = (const float*)d_in[9];
  const float* conv_b  = (const float*)d_in[10];
  const float* xproj   = (const float*)d_in[11];
  const float* dtw     = (const float*)d_in[12];
  const float* dtb     = (const float*)d_in[13];
  const float* Alog    = (const float*)d_in[14];
  const float* Dw      = (const float*)d_in[15];
  const float* norm_w  = (const float*)d_in[16];
  const float* norm_b  = (const float*)d_in[17];
  const float* out_w   = (const float*)d_in[18];
  const float* flnw    = (const float*)d_in[19];
  const float* flnb    = (const float*)d_in[20];
  const float* w1      = (const float*)d_in[21];
  const float* dw      = (const float*)d_in[22];
  const float* w2      = (const float*)d_in[23];
  float* out = (float*)d_out;

  const int attn_smem = (2*KTILE + 2*VTILE) * 4;
  const int ffn1_smem = 64*257*4;
  const int ffn2_smem = 256*65*4;
  cudaFuncSetAttribute(k_attn, cudaFuncAttributeMaxDynamicSharedMemorySize, attn_smem);
  cudaFuncSetAttribute(k_ssin, cudaFuncAttributeMaxDynamicSharedMemorySize, 65536);
  cudaFuncSetAttribute(k_ffn1, cudaFuncAttributeMaxDynamicSharedMemorySize, ffn1_smem);
  cudaFuncSetAttribute(k_ffn2, cudaFuncAttributeMaxDynamicSharedMemorySize, ffn2_smem);

  k_snr<<<(B_*L_ + 511)/512, 512>>>(snr);
  k_qkv<<<288, 512>>>(enc, wq, wk, wv);
  k_attn<<<dim3(18, 16), 256, attn_smem>>>();
  k_attn_epi<<<144, 256>>>(enc, fc, aln_w, aln_b);
  k_ssin<<<144, 256, 65536>>>(ss_in_w);
  k_dw1<<<(B_*DN_*L_ + 255)/256, 256>>>(conv_w, conv_b);
  k_xdbl<<<576, 256>>>(xproj, dtw, dtb);
  k_scan<<<512, 32>>>(Alog, Dw);
  k_merge<<<576, 128>>>(enc, snr, norm_w, norm_b, out_w, flnw, flnb);
  k_ffn1<<<144, 256, ffn1_smem>>>(w1);
  k_dw2<<<(B_*CM_*L_ + 255)/256, 256>>>(dw);
  k_ffn2<<<144, 256, ffn2_smem>>>(w2, out);
}

// round 9
// speedup vs baseline: 1.0518x; 1.0518x over previous
#include <cuda_runtime.h>
#include <math.h>

constexpr int B_ = 2, C_ = 64, Hh = 48, Ww = 48, L_ = 2304;
constexpr int NH_ = 8, DK_ = 64, DV_ = 128;
constexpr int DN_ = 128, NS_ = 16, CM_ = 256;

// ---------------- scratch ---------------------------------------------------
__device__ float g_q[B_*NH_*L_*DK_];
__device__ float g_k[B_*NH_*L_*DK_];
__device__ float g_v[B_*NH_*L_*DV_];
__device__ float g_snrlog[B_*L_];
__device__ float g_attno[B_*L_*NH_*DV_];
__device__ float g_enc[B_*L_*C_];
__device__ float g_z[B_*L_*DN_];
__device__ float g_x1[B_*DN_*L_];
__device__ float g_x1c[B_*DN_*L_];
__device__ float g_dts[B_*4*L_*DN_];
__device__ float g_Bs[B_*4*L_*NS_];
__device__ float g_Cs[B_*4*L_*NS_];
__device__ float g_ys[B_*4*L_*DN_];
__device__ float g_x2[B_*L_*C_];
__device__ float g_xn[B_*L_*C_];
__device__ float g_h1[B_*CM_*L_];
__device__ float g_h2[B_*CM_*L_];

__device__ __forceinline__ float warp_sum(float v) {
  #pragma unroll
  for (int o = 16; o > 0; o >>= 1) v += __shfl_xor_sync(0xffffffffu, v, o);
  return v;
}

__device__ __forceinline__ float gelu_exact(float x) {
  return 0.5f * x * (1.0f + erff(x * 0.70710678118654752f));
}

__device__ __forceinline__ unsigned f2r(float x) { return __float_as_uint(x); }

__device__ __forceinline__ void mma_tf32(float* d, const unsigned* a, unsigned b0, unsigned b1) {
  asm volatile("mma.sync.aligned.m16n8k8.row.col.f32.tf32.tf32.f32 "
    "{%0,%1,%2,%3}, {%4,%5,%6,%7}, {%8,%9}, {%0,%1,%2,%3};"
    : "+f"(d[0]), "+f"(d[1]), "+f"(d[2]), "+f"(d[3])
    : "r"(a[0]), "r"(a[1]), "r"(a[2]), "r"(a[3]), "r"(b0), "r"(b1));
}

__device__ __forceinline__ void cp16(unsigned s, const void* g) {
  asm volatile("cp.async.cg.shared.global [%0], [%1], 16;" :: "r"(s), "l"(g));
}

// ---------------- K0 --------------------------------------------------------
__global__ void k_snr(const float* __restrict__ snr) {
  int i = blockIdx.x*512 + threadIdx.x;
  if (i < B_*L_) g_snrlog[i] = logf(snr[i] + 1e-4f);
}

// ---------------- K1: QKV projection (R4 config) ---------------------------
__global__ void k_qkv(const float* __restrict__ x,
                      const float* __restrict__ wq,
                      const float* __restrict__ wk,
                      const float* __restrict__ wv) {
  __shared__ float sx[8][64];
  int blk = blockIdx.x;
  int b = blk / (L_/8);
  int t0 = (blk % (L_/8)) * 8;
  int tid = threadIdx.x;
  for (int i = tid; i < 512; i += 256) {
    int cc = i >> 3, tt = i & 7;
    sx[tt][cc] = x[(b*C_ + cc)*L_ + t0 + tt];
  }
  __syncthreads();
  int c0 = tid * 8;
  const float* wp;
  int stride;
  if (c0 < 512)       { wp = wq + c0;          stride = 512; }
  else if (c0 < 1024) { wp = wk + (c0 - 512);  stride = 512; }
  else                { wp = wv + (c0 - 1024); stride = 1024; }
  float acc[8][8];
  #pragma unroll
  for (int i = 0; i < 8; i++)
    #pragma unroll
    for (int j = 0; j < 8; j++) acc[i][j] = 0.f;
  for (int cc = 0; cc < 64; cc++) {
    float4 w0 = *(const float4*)&wp[cc*stride];
    float4 w1 = *(const float4*)&wp[cc*stride + 4];
    float w[8] = {w0.x, w0.y, w0.z, w0.w, w1.x, w1.y, w1.z, w1.w};
    #pragma unroll
    for (int tt = 0; tt < 8; tt++) {
      float xv = sx[tt][cc];
      #pragma unroll
      for (int j = 0; j < 8; j++) acc[tt][j] = fmaf(xv, w[j], acc[tt][j]);
    }
  }
  #pragma unroll
  for (int tt = 0; tt < 8; tt++) {
    int l = t0 + tt;
    float4 lo = {acc[tt][0], acc[tt][1], acc[tt][2], acc[tt][3]};
    float4 hi = {acc[tt][4], acc[tt][5], acc[tt][6], acc[tt][7]};
    if (c0 < 512) {
      int h = c0 >> 6, d = c0 & 63;
      float* p = &g_q[((b*NH_ + h)*L_ + l)*DK_ + d];
      *(float4*)p = lo; *(float4*)(p + 4) = hi;
    } else if (c0 < 1024) {
      int c2 = c0 - 512; int h = c2 >> 6, d = c2 & 63;
      float* p = &g_k[((b*NH_ + h)*L_ + l)*DK_ + d];
      *(float4*)p = lo; *(float4*)(p + 4) = hi;
    } else {
      int c2 = c0 - 1024; int h = c2 >> 7, d = c2 & 127;
      float* p = &g_v[((b*NH_ + h)*L_ + l)*DV_ + d];
      *(float4*)p = lo; *(float4*)(p + 4) = hi;
    }
  }
}

// ---------------- K2: flash attention, tf32 mma ----------------------------
constexpr int KSTR = 68;
constexpr int VSTR = 136;
constexpr int KTILE = 64*KSTR;
constexpr int VTILE = 64*VSTR;

__global__ void __launch_bounds__(256, 1) k_attn() {
  extern __shared__ float sm[];
  float* sKb[2] = { sm, sm + KTILE };
  float* sVb[2] = { sm + 2*KTILE, sm + 2*KTILE + VTILE };

  int tid = threadIdx.x;
  int wid = tid >> 5, lane = tid & 31;
  int g = lane >> 2, t = lane & 3;
  int bh = blockIdx.y;
  int b = bh >> 3, h = bh & 7;
  int q0 = blockIdx.x * 128;
  int m0 = wid * 16;

  unsigned smbase = (unsigned)__cvta_generic_to_shared(sm);

  unsigned qf[8][4];
  {
    const float* qp0 = g_q + ((size_t)bh*L_ + q0 + m0 + g)*64;
    const float* qp1 = qp0 + 8*64;
    #pragma unroll
    for (int ks = 0; ks < 8; ks++) {
      qf[ks][0] = f2r(qp0[8*ks + t]);
      qf[ks][1] = f2r(qp1[8*ks + t]);
      qf[ks][2] = f2r(qp0[8*ks + t + 4]);
      qf[ks][3] = f2r(qp1[8*ks + t + 4]);
    }
  }

  float oacc[16][4];
  #pragma unroll
  for (int j = 0; j < 16; j++)
    #pragma unroll
    for (int r = 0; r < 4; r++) oacc[j][r] = 0.f;
  float mrun0 = -1e30f, mrun1 = -1e30f, l0 = 0.f, l1 = 0.f;

  const float* snrl = g_snrlog + b*L_;

  {
    const float* kp = g_k + ((size_t)bh*L_)*64;
    const float* vp = g_v + ((size_t)bh*L_)*128;
    unsigned kS = smbase;
    unsigned vS = smbase + 2*KTILE*4;
    #pragma unroll
    for (int i = 0; i < 4; i++) {
      int idx = tid + 256*i; int row = idx >> 4, ch = idx & 15;
      cp16(kS + (row*KSTR + ch*4)*4, kp + row*64 + ch*4);
    }
    #pragma unroll
    for (int i = 0; i < 8; i++) {
      int idx = tid + 256*i; int row = idx >> 5, ch = idx & 31;
      cp16(vS + (row*VSTR + ch*4)*4, vp + row*128 + ch*4);
    }
  }
  asm volatile("cp.async.commit_group;");

  int stage = 0;
  for (int kt = 0; kt < 36; kt++) {
    if (kt + 1 < 36) {
      int kv1 = (kt + 1) * 64;
      const float* kp = g_k + ((size_t)bh*L_ + kv1)*64;
      const float* vp = g_v + ((size_t)bh*L_ + kv1)*128;
      int st = stage ^ 1;
      unsigned kS = smbase + (unsigned)(st*KTILE)*4;
      unsigned vS = smbase + (unsigned)(2*KTILE + st*VTILE)*4;
      #pragma unroll
      for (int i = 0; i < 4; i++) {
        int idx = tid + 256*i; int row = idx >> 4, ch = idx & 15;
        cp16(kS + (row*KSTR + ch*4)*4, kp + row*64 + ch*4);
      }
      #pragma unroll
      for (int i = 0; i < 8; i++) {
        int idx = tid + 256*i; int row = idx >> 5, ch = idx & 31;
        cp16(vS + (row*VSTR + ch*4)*4, vp + row*128 + ch*4);
      }
    }
    asm volatile("cp.async.commit_group;");
    asm volatile("cp.async.wait_group 1;");
    __syncthreads();

    const float* sK = sKb[stage];
    const float* sV = sVb[stage];
    int kv0 = kt * 64;

    float sacc[8][4];
    #pragma unroll
    for (int j = 0; j < 8; j++)
      #pragma unroll
      for (int r = 0; r < 4; r++) sacc[j][r] = 0.f;
    #pragma unroll
    for (int ks = 0; ks < 8; ks++) {
      #pragma unroll
      for (int j = 0; j < 8; j++) {
        unsigned b0 = f2r(sK[(8*j + g)*KSTR + 8*ks + t]);
        unsigned b1 = f2r(sK[(8*j + g)*KSTR + 8*ks + t + 4]);
        mma_tf32(sacc[j], qf[ks], b0, b1);
      }
    }

    #pragma unroll
    for (int j = 0; j < 8; j++) {
      float2 sb = *(const float2*)&snrl[kv0 + 8*j + 2*t];
      sacc[j][0] = sacc[j][0]*0.125f + sb.x;
      sacc[j][1] = sacc[j][1]*0.125f + sb.y;
      sacc[j][2] = sacc[j][2]*0.125f + sb.x;
      sacc[j][3] = sacc[j][3]*0.125f + sb.y;
    }

    float m0l = -1e30f, m1l = -1e30f;
    #pragma unroll
    for (int j = 0; j < 8; j++) {
      m0l = fmaxf(m0l, fmaxf(sacc[j][0], sacc[j][1]));
      m1l = fmaxf(m1l, fmaxf(sacc[j][2], sacc[j][3]));
    }
    m0l = fmaxf(m0l, __shfl_xor_sync(0xffffffffu, m0l, 1));
    m0l = fmaxf(m0l, __shfl_xor_sync(0xffffffffu, m0l, 2));
    m1l = fmaxf(m1l, __shfl_xor_sync(0xffffffffu, m1l, 1));
    m1l = fmaxf(m1l, __shfl_xor_sync(0xffffffffu, m1l, 2));
    float m0n = fmaxf(mrun0, m0l), m1n = fmaxf(mrun1, m1l);
    float sc0 = __expf(mrun0 - m0n), sc1 = __expf(mrun1 - m1n);
    float s0 = 0.f, s1 = 0.f;
    #pragma unroll
    for (int j = 0; j < 8; j++) {
      float p0 = __expf(sacc[j][0] - m0n);
      float p1 = __expf(sacc[j][1] - m0n);
      float p2 = __expf(sacc[j][2] - m1n);
      float p3 = __expf(sacc[j][3] - m1n);
      sacc[j][0] = p0; sacc[j][1] = p1; sacc[j][2] = p2; sacc[j][3] = p3;
      s0 += p0 + p1; s1 += p2 + p3;
    }
    s0 += __shfl_xor_sync(0xffffffffu, s0, 1);
    s0 += __shfl_xor_sync(0xffffffffu, s0, 2);
    s1 += __shfl_xor_sync(0xffffffffu, s1, 1);
    s1 += __shfl_xor_sync(0xffffffffu, s1, 2);
    l0 = l0*sc0 + s0; l1 = l1*sc1 + s1;
    mrun0 = m0n; mrun1 = m1n;
    #pragma unroll
    for (int j = 0; j < 16; j++) {
      oacc[j][0] *= sc0; oacc[j][1] *= sc0;
      oacc[j][2] *= sc1; oacc[j][3] *= sc1;
    }

    int srcA = (lane & 28) | (t >> 1);
    int srcB = srcA + 2;
    bool odd = (t & 1);
    #pragma unroll
    for (int ks = 0; ks < 8; ks++) {
      float c0 = sacc[ks][0], c1 = sacc[ks][1], c2 = sacc[ks][2], c3 = sacc[ks][3];
      float r0 = __shfl_sync(0xffffffffu, c0, srcA);
      float r1 = __shfl_sync(0xffffffffu, c1, srcA);
      float r2 = __shfl_sync(0xffffffffu, c0, srcB);
      float r3 = __shfl_sync(0xffffffffu, c1, srcB);
      float r4 = __shfl_sync(0xffffffffu, c2, srcA);
      float r5 = __shfl_sync(0xffffffffu, c3, srcA);
      float r6 = __shfl_sync(0xffffffffu, c2, srcB);
      float r7 = __shfl_sync(0xffffffffu, c3, srcB);
      unsigned pa[4];
      pa[0] = f2r(odd ? r1 : r0);
      pa[1] = f2r(odd ? r5 : r4);
      pa[2] = f2r(odd ? r3 : r2);
      pa[3] = f2r(odd ? r7 : r6);
      const float* v0 = sV + (8*ks + t)*VSTR + g;
      const float* v1 = sV + (8*ks + t + 4)*VSTR + g;
      #pragma unroll
      for (int j2 = 0; j2 < 16; j2++) {
        unsigned b0 = f2r(v0[8*j2]);
        unsigned b1 = f2r(v1[8*j2]);
        mma_tf32(oacc[j2], pa, b0, b1);
      }
    }
    stage ^= 1;
    __syncthreads();
  }

  float inv0 = 1.f / l0, inv1 = 1.f / l1;
  int row0 = q0 + m0 + g;
  float* op0 = g_attno + ((size_t)(b*L_ + row0))*1024 + h*128;
  float* op1 = op0 + (size_t)8*1024;
  #pragma unroll
  for (int j2 = 0; j2 < 16; j2++) {
    float2 v0 = { oacc[j2][0]*inv0, oacc[j2][1]*inv0 };
    float2 v1 = { oacc[j2][2]*inv1, oacc[j2][3]*inv1 };
    *(float2*)&op0[8*j2 + 2*t] = v0;
    *(float2*)&op1[8*j2 + 2*t] = v1;
  }
}

// ---------------- K3: attn out proj + residual + LN ------------------------
// grid 288 (16 tokens/block), block 128. A tile fully resident (cp.async),
// fc weight chunks double-buffered via cp.async -> barriers close on arrived data.
__global__ void __launch_bounds__(128) k_attn_epi(const float* __restrict__ x,
                           const float* __restrict__ fc,
                           const float* __restrict__ lnw,
                           const float* __restrict__ lnb) {
  extern __shared__ float smep[];
  float* sA  = smep;                 // [tok][k] stride 1028 (16 x 1028)
  float* sB0 = smep + 16*1028;       // [kk][c] stride 68
  float* sB1 = sB0 + 64*68;
  __shared__ float sout[16][64];
  int blk = blockIdx.x;
  int b = blk / 144;
  int t0 = (blk % 144) * 16;
  int tid = threadIdx.x;
  unsigned sbase = (unsigned)__cvta_generic_to_shared(smep);
  unsigned bbase[2] = { sbase + 16*1028*4, sbase + (16*1028 + 64*68)*4 };

  // stage A (16 x 1024) + B chunk 0, one group
  for (int i = tid*4; i < 16384; i += 512) {
    int tok = i >> 10, k = i & 1023;
    cp16(sbase + (unsigned)(tok*1028 + k)*4,
         &g_attno[((size_t)(b*L_ + t0 + tok))*1024 + k]);
  }
  for (int i = tid*4; i < 4096; i += 512) {
    int kk = i >> 6, c = i & 63;
    cp16(bbase[0] + (unsigned)(kk*68 + c)*4, &fc[(size_t)kk*64 + c]);
  }
  asm volatile("cp.async.commit_group;");

  int cg = tid & 15, tg = tid >> 4;      // cg: 4 channels, tg: 2 tokens
  float acc[2][4];
  #pragma unroll
  for (int u = 0; u < 2; u++)
    #pragma unroll
    for (int r = 0; r < 4; r++) acc[u][r] = 0.f;

  int buf = 0;
  for (int kc = 0; kc < 16; kc++) {
    if (kc + 1 < 16) {
      for (int i = tid*4; i < 4096; i += 512) {
        int kk = i >> 6, c = i & 63;
        cp16(bbase[buf ^ 1] + (unsigned)(kk*68 + c)*4,
             &fc[(size_t)((kc + 1)*64 + kk)*64 + c]);
      }
      asm volatile("cp.async.commit_group;");
      asm volatile("cp.async.wait_group 1;");
    } else {
      asm volatile("cp.async.wait_group 0;");
    }
    __syncthreads();
    const float* sB = buf ? sB1 : sB0;
    int kb = kc*64;
    #pragma unroll 4
    for (int kk = 0; kk < 64; kk++) {
      float4 w = *(const float4*)&sB[kk*68 + cg*4];
      float x0 = sA[(tg*2)*1028 + kb + kk];
      float x1 = sA[(tg*2 + 1)*1028 + kb + kk];
      acc[0][0] = fmaf(x0, w.x, acc[0][0]); acc[0][1] = fmaf(x0, w.y, acc[0][1]);
      acc[0][2] = fmaf(x0, w.z, acc[0][2]); acc[0][3] = fmaf(x0, w.w, acc[0][3]);
      acc[1][0] = fmaf(x1, w.x, acc[1][0]); acc[1][1] = fmaf(x1, w.y, acc[1][1]);
      acc[1][2] = fmaf(x1, w.z, acc[1][2]); acc[1][3] = fmaf(x1, w.w, acc[1][3]);
    }
    buf ^= 1;
    __syncthreads();
  }
  #pragma unroll
  for (int u = 0; u < 2; u++) {
    int tok = tg*2 + u;
    #pragma unroll
    for (int r = 0; r < 4; r++) {
      int c = cg*4 + r;
      sout[tok][c] = acc[u][r] + x[(b*C_ + c)*L_ + t0 + tok];
    }
  }
  __syncthreads();
  int lane = tid & 31, wid = tid >> 5;
  for (int tok = wid; tok < 16; tok += 4) {
    float v0 = sout[tok][lane], v1 = sout[tok][lane + 32];
    float mean = warp_sum(v0 + v1) * (1.f/64.f);
    float d0 = v0 - mean, d1 = v1 - mean;
    float var = warp_sum(d0*d0 + d1*d1) * (1.f/64.f);
    float rs = rsqrtf(var + 1e-5f);
    int l = t0 + tok;
    g_enc[(b*L_ + l)*64 + lane]      = d0*rs*lnw[lane] + lnb[lane];
    g_enc[(b*L_ + l)*64 + lane + 32] = d1*rs*lnw[lane + 32] + lnb[lane + 32];
  }
}

// ---------------- K4: SS input projection (R4 config) ----------------------
__global__ void k_ssin(const float* __restrict__ w) {
  extern __shared__ float sw[];
  __shared__ float sxe[16][64];
  int blk = blockIdx.x;
  int b = blk / (L_/16);
  int t0 = (blk % (L_/16)) * 16;
  int tid = threadIdx.x;
  for (int i = tid*4; i < 16384; i += 1024)
    *(float4*)&sw[i] = *(const float4*)&w[i];
  for (int i = tid; i < 1024; i += 256)
    sxe[i>>6][i&63] = g_enc[(b*L_ + t0 + (i>>6))*64 + (i&63)];
  __syncthreads();
  int tok = tid >> 4, c0 = tid & 15;
  float acc[16];
  #pragma unroll
  for (int j = 0; j < 16; j++) acc[j] = 0.f;
  for (int cc = 0; cc < 64; cc++) {
    float xv = sxe[tok][cc];
    #pragma unroll
    for (int j = 0; j < 16; j++) acc[j] = fmaf(xv, sw[cc*256 + c0 + 16*j], acc[j]);
  }
  int l = t0 + tok;
  #pragma unroll
  for (int j = 0; j < 16; j++) {
    int c = c0 + 16*j;
    if (c < 128) g_x1[(b*128 + c)*L_ + l] = acc[j];
    else         g_z[(b*L_ + l)*128 + (c - 128)] = acc[j];
  }
}

// ---------------- K5: depthwise conv3x3 + bias + silu ----------------------
__global__ void k_dw1(const float* __restrict__ w, const float* __restrict__ bias) {
  int p = blockIdx.x*256 + threadIdx.x;
  if (p >= B_*DN_*L_) return;
  int b = p / (DN_*L_);
  int rem = p - b*DN_*L_;
  int d = rem / L_;
  int hw = rem - d*L_;
  int i = hw / Ww, j = hw - i*Ww;
  const float* src = g_x1 + (b*DN_ + d)*L_;
  const float* wr = w + d*9;
  float acc = bias[d];
  #pragma unroll
  for (int kh = -1; kh <= 1; kh++) {
    int ih = i + kh;
    if (ih < 0 || ih >= Hh) continue;
    #pragma unroll
    for (int kw = -1; kw <= 1; kw++) {
      int iw = j + kw;
      if (iw < 0 || iw >= Ww) continue;
      acc = fmaf(src[ih*Ww + iw], wr[(kh+1)*3 + (kw+1)], acc);
    }
  }
  float s = acc / (1.f + __expf(-acc));
  g_x1c[(b*DN_ + d)*L_ + hw] = s;
}

__device__ __forceinline__ int xs_src(int k, int l) {
  if (k == 0) return l;
  int i = l / 48, j = l - i*48;
  if (k == 1) return j*48 + i;
  if (k == 2) return L_ - 1 - l;
  return (47 - j)*48 + (47 - i);
}

// ---------------- K6: x_dbl projection + dt proj + softplus (R4 config) ----
__global__ void k_xdbl(const float* __restrict__ xw,
                       const float* __restrict__ dtw,
                       const float* __restrict__ dtb) {
  __shared__ float sxs[16][130];
  __shared__ float sxw[128][37];
  __shared__ float sdt[16][4];
  __shared__ float sdtw[128][5];
  __shared__ float sdtbv[128];
  int t = blockIdx.x;
  int lt = t % 144;
  int k = (t / 144) & 3;
  int b = t / 576;
  int l0 = lt * 16;
  int tid = threadIdx.x;
  for (int i = tid; i < 4608; i += 256) {
    int c = i >> 7, d = i & 127;
    sxw[d][c] = xw[(size_t)k*4608 + i];
  }
  for (int i = tid; i < 512; i += 256) {
    int d = i >> 2, r = i & 3;
    sdtw[d][r] = dtw[(size_t)k*512 + i];
  }
  if (tid < 128) sdtbv[tid] = dtb[k*128 + tid];
  for (int i3 = tid; i3 < 2048; i3 += 256) {
    int tt = i3 >> 7, d = i3 & 127;
    int src = xs_src(k, l0 + tt);
    sxs[tt][d] = g_x1c[(b*128 + d)*L_ + src];
  }
  __syncthreads();
  for (int o = tid; o < 16*36; o += 256) {
    int ll = o / 36, c = o - ll*36;
    float acc = 0.f;
    #pragma unroll 4
    for (int d = 0; d < 128; d++) acc = fmaf(sxs[ll][d], sxw[d][c], acc);
    int l = l0 + ll;
    if (c < 4)       sdt[ll][c] = acc;
    else if (c < 20) g_Bs[((b*4 + k)*L_ + l)*16 + (c - 4)]  = acc;
    else             g_Cs[((b*4 + k)*L_ + l)*16 + (c - 20)] = acc;
  }
  __syncthreads();
  for (int o = tid; o < 16*128; o += 256) {
    int ll = o >> 7, d = o & 127;
    float acc = sdtbv[d];
    #pragma unroll
    for (int r = 0; r < 4; r++) acc = fmaf(sdt[ll][r], sdtw[d][r], acc);
    float sp = (acc > 20.f) ? acc : log1pf(__expf(acc));
    g_dts[((b*4 + k)*L_ + l0 + ll)*128 + d] = sp;
  }
}

// ---------------- K7: selective scan ---------------------------------------
__global__ void k_scan(const float* __restrict__ Alog, const float* __restrict__ Dw) {
  int gw = blockIdx.x;
  int lane = threadIdx.x;
  int b = gw >> 8;
  int rem = gw & 255;
  int k = rem >> 6;
  int dp = rem & 63;
  int n = lane & 15;
  int d = dp*2 + (lane >> 4);

  float An = -__expf(Alog[(k*128 + d)*16 + n]);
  float Dd = Dw[k*128 + d];
  const float* dtp = g_dts + ((size_t)(b*4 + k)*L_)*128 + d;
  const float* Bp  = g_Bs  + ((size_t)(b*4 + k)*L_)*16 + n;
  const float* Cp  = g_Cs  + ((size_t)(b*4 + k)*L_)*16 + n;
  float*       yp  = g_ys  + ((size_t)(b*4 + k)*L_)*128 + d;
  const float* xp  = g_x1c + (b*128 + d)*L_;

  float hst = 0.f;
  int ii = 0, jj = 0;
  for (int l0 = 0; l0 < L_; l0 += 8) {
    float dt[8], xv[8], Bn[8], Cn[8];
    #pragma unroll
    for (int u = 0; u < 8; u++) {
      int l = l0 + u;
      int src;
      if (k == 0)      src = l;
      else if (k == 1) src = jj*48 + ii;
      else if (k == 2) src = L_ - 1 - l;
      else             src = (47 - jj)*48 + (47 - ii);
      dt[u] = dtp[l*128];
      xv[u] = xp[src];
      Bn[u] = Bp[l*16];
      Cn[u] = Cp[l*16];
      jj++;
      if (jj == 48) { jj = 0; ii++; }
    }
    #pragma unroll
    for (int u = 0; u < 8; u++) {
      float dA = __expf(dt[u] * An);
      hst = fmaf(hst, dA, dt[u]*xv[u]*Bn[u]);
      float y = hst * Cn[u];
      y += __shfl_xor_sync(0xffffffffu, y, 1);
      y += __shfl_xor_sync(0xffffffffu, y, 2);
      y += __shfl_xor_sync(0xffffffffu, y, 4);
      y += __shfl_xor_sync(0xffffffffu, y, 8);
      if (n == 0) yp[(l0 + u)*128] = fmaf(Dd, xv[u], y);
    }
  }
}

// ---------------- K8: merge + LN + gate + out proj + LN (R4 config) --------
__global__ void __launch_bounds__(128) k_merge(const float* __restrict__ x,
                        const float* __restrict__ snr,
                        const float* __restrict__ nw, const float* __restrict__ nb,
                        const float* __restrict__ ow,
                        const float* __restrict__ flnw, const float* __restrict__ flnb) {
  __shared__ float sow[128*64];
  __shared__ float sy[128];
  __shared__ float red[4], red2[4];
  __shared__ float spart[2][64];
  int blk = blockIdx.x;
  int b = blk / 288;
  int t0 = (blk % 288) * 8;
  int tid = threadIdx.x, lane = tid & 31, wid = tid >> 5;
  for (int i = tid*4; i < 8192; i += 512)
    *(float4*)&sow[i] = *(const float4*)&ow[i];
  size_t base = (size_t)b*4*L_*128;
  float nwv = nw[tid], nbv = nb[tid];
  __syncthreads();

  for (int tok = 0; tok < 8; tok++) {
    int l = t0 + tok;
    int i = l / 48, j = l - i*48;
    int lt = j*48 + i;
    float y = g_ys[base + ((size_t)0*L_ + l)*128 + tid]
            + g_ys[base + ((size_t)2*L_ + (L_ - 1 - l))*128 + tid]
            + g_ys[base + ((size_t)1*L_ + lt)*128 + tid]
            + g_ys[base + ((size_t)3*L_ + (L_ - 1 - lt))*128 + tid];
    float s1 = warp_sum(y), s2 = warp_sum(y*y);
    if (lane == 0) { red[wid] = s1; red2[wid] = s2; }
    __syncthreads();
    float mean = (red[0] + red[1] + red[2] + red[3]) * (1.f/128.f);
    float var  = fmaxf((red2[0] + red2[1] + red2[2] + red2[3]) * (1.f/128.f) - mean*mean, 0.f);
    float yn = (y - mean) * rsqrtf(var + 1e-5f) * nwv + nbv;
    float z = g_z[(b*L_ + l)*128 + tid];
    float sz = z / (1.f + __expf(-z));
    float sv = snr[b*L_ + l];
    sy[tid] = yn * sz * sv;
    __syncthreads();
    {
      int c = tid & 63, half = tid >> 6;
      float acc = 0.f;
      int d0 = half*64;
      #pragma unroll 8
      for (int d = 0; d < 64; d++) acc = fmaf(sy[d0 + d], sow[(d0 + d)*64 + c], acc);
      spart[half][c] = acc;
    }
    __syncthreads();
    float v = 0.f;
    if (tid < 64) {
      v = spart[0][tid] + spart[1][tid] + x[(b*C_ + tid)*L_ + l];
      g_x2[(b*L_ + l)*64 + tid] = v;
    }
    float t1 = warp_sum(tid < 64 ? v : 0.f);
    float t2 = warp_sum(tid < 64 ? v*v : 0.f);
    if (lane == 0) { red[wid] = t1; red2[wid] = t2; }
    __syncthreads();
    float mean2 = (red[0] + red[1]) * (1.f/64.f);
    float var2  = fmaxf((red2[0] + red2[1]) * (1.f/64.f) - mean2*mean2, 0.f);
    if (tid < 64)
      g_xn[(b*L_ + l)*64 + tid] = (v - mean2) * rsqrtf(var2 + 1e-5f) * flnw[tid] + flnb[tid];
    __syncthreads();
  }
}

// ---------------- K9: FFN conv1x1 64->256 + gelu (R4 config) ---------------
__global__ void k_ffn1(const float* __restrict__ w1) {
  extern __shared__ float sw1[];
  __shared__ float sx[16][64];
  int blk = blockIdx.x;
  int b = blk / (L_/16);
  int t0 = (blk % (L_/16)) * 16;
  int tid = threadIdx.x;
  for (int i = tid; i < 16384; i += 256) {
    int oc = i >> 6, cc = i & 63;
    sw1[cc*257 + oc] = w1[i];
  }
  for (int i = tid; i < 1024; i += 256) {
    int tt = i >> 6, cc = i & 63;
    sx[tt][cc] = g_xn[(b*L_ + t0 + tt)*64 + cc];
  }
  __syncthreads();
  int oc = tid;
  float acc[16];
  #pragma unroll
  for (int q = 0; q < 16; q++) acc[q] = 0.f;
  for (int cc = 0; cc < 64; cc++) {
    float w = sw1[cc*257 + oc];
    #pragma unroll
    for (int q = 0; q < 16; q++) acc[q] = fmaf(sx[q][cc], w, acc[q]);
  }
  float* dst = g_h1 + (b*CM_ + oc)*L_ + t0;
  #pragma unroll
  for (int q = 0; q < 16; q++) dst[q] = gelu_exact(acc[q]);
}

// ---------------- K10: FFN depthwise conv3x3 + gelu ------------------------
__global__ void k_dw2(const float* __restrict__ w) {
  int p = blockIdx.x*256 + threadIdx.x;
  if (p >= B_*CM_*L_) return;
  int b = p / (CM_*L_);
  int rem = p - b*CM_*L_;
  int ch = rem / L_;
  int hw = rem - ch*L_;
  int i = hw / Ww, j = hw - i*Ww;
  const float* src = g_h1 + (b*CM_ + ch)*L_;
  const float* wr = w + ch*9;
  float acc = 0.f;
  #pragma unroll
  for (int kh = -1; kh <= 1; kh++) {
    int ih = i + kh;
    if (ih < 0 || ih >= Hh) continue;
    #pragma unroll
    for (int kw = -1; kw <= 1; kw++) {
      int iw = j + kw;
      if (iw < 0 || iw >= Ww) continue;
      acc = fmaf(src[ih*Ww + iw], wr[(kh+1)*3 + (kw+1)], acc);
    }
  }
  g_h2[(b*CM_ + ch)*L_ + hw] = gelu_exact(acc);
}

// ---------------- K11: FFN conv1x1 256->64 + residual (R4 config) ----------
__global__ void k_ffn2(const float* __restrict__ w2, float* __restrict__ out) {
  extern __shared__ float sw2[];
  __shared__ float sh[256][16];
  int blk = blockIdx.x;
  int b = blk / (L_/16);
  int t0 = (blk % (L_/16)) * 16;
  int tid = threadIdx.x;
  for (int i = tid; i < 16384; i += 256) {
    int c = i >> 8, oc = i & 255;
    sw2[oc*65 + c] = w2[i];
  }
  for (int i = tid; i < 4096; i += 256) {
    int oc = i >> 4, tt = i & 15;
    sh[oc][tt] = g_h2[(b*CM_ + oc)*L_ + t0 + tt];
  }
  __syncthreads();
  int c = tid & 63, tg = tid >> 6;
  float acc[4] = {0.f, 0.f, 0.f, 0.f};
  for (int oc = 0; oc < 256; oc++) {
    float w = sw2[oc*65 + c];
    #pragma unroll
    for (int q = 0; q < 4; q++) acc[q] = fmaf(sh[oc][tg + 4*q], w, acc[q]);
  }
  #pragma unroll
  for (int q = 0; q < 4; q++) {
    int l = t0 + tg + 4*q;
    out[(b*C_ + c)*L_ + l] = acc[q] + g_x2[(b*L_ + l)*64 + c];
  }
}

// ---------------- launch ----------------------------------------------------
extern "C" void kernel_launch(void* const* d_in, const int* in_sizes, int n_in,
                              void* d_out, int out_size) {
  const float* enc     = (const float*)d_in[0];
  const float* snr     = (const float*)d_in[1];
  const float* wq      = (const float*)d_in[2];
  const float* wk      = (const float*)d_in[3];
  const float* wv      = (const float*)d_in[4];
  const float* fc      = (const float*)d_in[5];
  const float* aln_w   = (const float*)d_in[6];
  const float* aln_b   = (const float*)d_in[7];
  const float* ss_in_w = (const float*)d_in[8];
  const float* conv_w  = (const float*)d_in[9];
  const float* conv_b  = (const float*)d_in[10];
  const float* xproj   = (const float*)d_in[11];
  const float* dtw     = (const float*)d_in[12];
  const float* dtb     = (const float*)d_in[13];
  const float* Alog    = (const float*)d_in[14];
  const float* Dw      = (const float*)d_in[15];
  const float* norm_w  = (const float*)d_in[16];
  const float* norm_b  = (const float*)d_in[17];
  const float* out_w   = (const float*)d_in[18];
  const float* flnw    = (const float*)d_in[19];
  const float* flnb    = (const float*)d_in[20];
  const float* w1      = (const float*)d_in[21];
  const float* dw      = (const float*)d_in[22];
  const float* w2      = (const float*)d_in[23];
  float* out = (float*)d_out;

  const int attn_smem = (2*KTILE + 2*VTILE) * 4;              // 104448 B
  const int epi_smem  = (16*1028 + 2*64*68) * 4;              // 100608 B
  const int ffn1_smem = 64*257*4;
  const int ffn2_smem = 256*65*4;
  cudaFuncSetAttribute(k_attn, cudaFuncAttributeMaxDynamicSharedMemorySize, attn_smem);
  cudaFuncSetAttribute(k_attn_epi, cudaFuncAttributeMaxDynamicSharedMemorySize, epi_smem);
  cudaFuncSetAttribute(k_ssin, cudaFuncAttributeMaxDynamicSharedMemorySize, 65536);
  cudaFuncSetAttribute(k_ffn1, cudaFuncAttributeMaxDynamicSharedMemorySize, ffn1_smem);
  cudaFuncSetAttribute(k_ffn2, cudaFuncAttributeMaxDynamicSharedMemorySize, ffn2_smem);

  k_snr<<<(B_*L_ + 511)/512, 512>>>(snr);
  k_qkv<<<576, 256>>>(enc, wq, wk, wv);
  k_attn<<<dim3(18, 16), 256, attn_smem>>>();
  k_attn_epi<<<288, 128, epi_smem>>>(enc, fc, aln_w, aln_b);
  k_ssin<<<288, 256, 65536>>>(ss_in_w);
  k_dw1<<<(B_*DN_*L_ + 255)/256, 256>>>(conv_w, conv_b);
  k_xdbl<<<1152, 256>>>(xproj, dtw, dtb);
  k_scan<<<512, 32>>>(Alog, Dw);
  k_merge<<<576, 128>>>(enc, snr, norm_w, norm_b, out_w, flnw, flnb);
  k_ffn1<<<288, 256, ffn1_smem>>>(w1);
  k_dw2<<<(B_*CM_*L_ + 255)/256, 256>>>(dw);
  k_ffn2<<<288, 256, ffn2_smem>>>(w2, out);
}

// round 10
// speedup vs baseline: 1.3641x; 1.2970x over previous
#include <cuda_runtime.h>
#include <cuda_bf16.h>
#include <math.h>

constexpr int B_ = 2, C_ = 64, Hh = 48, Ww = 48, L_ = 2304;
constexpr int NH_ = 8, DK_ = 64, DV_ = 128;
constexpr int DN_ = 128, NS_ = 16, CM_ = 256;

// ---------------- scratch ---------------------------------------------------
__device__ __nv_bfloat16 g_qb[B_*NH_*L_*DK_];    // [bh][l][64]
__device__ __nv_bfloat16 g_kb[B_*NH_*L_*DK_];    // [bh][l][64]
__device__ __nv_bfloat16 g_vb[B_*NH_*DV_*L_];    // [bh][d][L]  (transposed!)
__device__ float g_snrlog[B_*L_];
__device__ float g_attno[B_*L_*NH_*DV_];
__device__ float g_enc[B_*L_*C_];
__device__ float g_z[B_*L_*DN_];
__device__ float g_x1[B_*DN_*L_];
__device__ float g_x1c[B_*DN_*L_];
__device__ float g_dts[B_*4*L_*DN_];
__device__ float g_Bs[B_*4*L_*NS_];
__device__ float g_Cs[B_*4*L_*NS_];
__device__ float g_ys[B_*4*L_*DN_];
__device__ float g_x2[B_*L_*C_];
__device__ float g_xn[B_*L_*C_];
__device__ float g_h1[B_*CM_*L_];
__device__ float g_h2[B_*CM_*L_];

__device__ __forceinline__ float warp_sum(float v) {
  #pragma unroll
  for (int o = 16; o > 0; o >>= 1) v += __shfl_xor_sync(0xffffffffu, v, o);
  return v;
}

__device__ __forceinline__ float gelu_exact(float x) {
  return 0.5f * x * (1.0f + erff(x * 0.70710678118654752f));
}

// pack (lo, hi) floats -> bf16x2
__device__ __forceinline__ unsigned pk(float lo, float hi) {
  unsigned r;
  asm("cvt.rn.bf16x2.f32 %0, %1, %2;" : "=r"(r) : "f"(hi), "f"(lo));
  return r;
}

__device__ __forceinline__ void mma_bf16(float* d, const unsigned* a, unsigned b0, unsigned b1) {
  asm volatile("mma.sync.aligned.m16n8k16.row.col.f32.bf16.bf16.f32 "
    "{%0,%1,%2,%3}, {%4,%5,%6,%7}, {%8,%9}, {%0,%1,%2,%3};"
    : "+f"(d[0]), "+f"(d[1]), "+f"(d[2]), "+f"(d[3])
    : "r"(a[0]), "r"(a[1]), "r"(a[2]), "r"(a[3]), "r"(b0), "r"(b1));
}

__device__ __forceinline__ void cp16(unsigned s, const void* g) {
  asm volatile("cp.async.cg.shared.global [%0], [%1], 16;" :: "r"(s), "l"(g));
}

// ---------------- K1: QKV projection (+ snr log fused) ---------------------
__global__ void k_qkv(const float* __restrict__ x,
                      const float* __restrict__ wq,
                      const float* __restrict__ wk,
                      const float* __restrict__ wv,
                      const float* __restrict__ snr) {
  __shared__ float sx[8][64];
  int blk = blockIdx.x;
  int b = blk / (L_/8);
  int t0 = (blk % (L_/8)) * 8;
  int tid = threadIdx.x;
  for (int i = tid; i < 512; i += 256) {
    int cc = i >> 3, tt = i & 7;
    sx[tt][cc] = x[(b*C_ + cc)*L_ + t0 + tt];
  }
  if (tid < 8) g_snrlog[b*L_ + t0 + tid] = logf(snr[b*L_ + t0 + tid] + 1e-4f);
  __syncthreads();
  int c0 = tid * 8;
  const float* wp;
  int stride;
  if (c0 < 512)       { wp = wq + c0;          stride = 512; }
  else if (c0 < 1024) { wp = wk + (c0 - 512);  stride = 512; }
  else                { wp = wv + (c0 - 1024); stride = 1024; }
  float acc[8][8];
  #pragma unroll
  for (int i = 0; i < 8; i++)
    #pragma unroll
    for (int j = 0; j < 8; j++) acc[i][j] = 0.f;
  for (int cc = 0; cc < 64; cc++) {
    float4 w0 = *(const float4*)&wp[cc*stride];
    float4 w1 = *(const float4*)&wp[cc*stride + 4];
    float w[8] = {w0.x, w0.y, w0.z, w0.w, w1.x, w1.y, w1.z, w1.w};
    #pragma unroll
    for (int tt = 0; tt < 8; tt++) {
      float xv = sx[tt][cc];
      #pragma unroll
      for (int j = 0; j < 8; j++) acc[tt][j] = fmaf(xv, w[j], acc[tt][j]);
    }
  }
  if (c0 < 1024) {
    // Q/K: row-major [bh][l][64] bf16, 16B per token
    #pragma unroll
    for (int tt = 0; tt < 8; tt++) {
      int l = t0 + tt;
      uint4 pkd = { pk(acc[tt][0], acc[tt][1]), pk(acc[tt][2], acc[tt][3]),
                    pk(acc[tt][4], acc[tt][5]), pk(acc[tt][6], acc[tt][7]) };
      if (c0 < 512) {
        int h = c0 >> 6, d = c0 & 63;
        *(uint4*)&g_qb[((size_t)(b*NH_ + h)*L_ + l)*DK_ + d] = pkd;
      } else {
        int c2 = c0 - 512; int h = c2 >> 6, d = c2 & 63;
        *(uint4*)&g_kb[((size_t)(b*NH_ + h)*L_ + l)*DK_ + d] = pkd;
      }
    }
  } else {
    // V: transposed [bh][d][L] bf16; pack 8 tokens per row
    int c2 = c0 - 1024; int h = c2 >> 7, d0 = c2 & 127;
    #pragma unroll
    for (int j = 0; j < 8; j++) {
      uint4 pkd = { pk(acc[0][j], acc[1][j]), pk(acc[2][j], acc[3][j]),
                    pk(acc[4][j], acc[5][j]), pk(acc[6][j], acc[7][j]) };
      *(uint4*)&g_vb[((size_t)(b*NH_ + h)*DV_ + d0 + j)*L_ + t0] = pkd;
    }
  }
}

// ---------------- K2: flash attention, bf16 m16n8k16 -----------------------
// smem (bf16 units): K tiles 64x72, V^T tiles 128x72, double buffered
constexpr int KU = 4608;      // 64*72
constexpr int VU = 9216;      // 128*72
// layout: [K0][K1][V0][V1] => offsets 0, 4608, 9216, 18432 (units); 55296 B total

__global__ void __launch_bounds__(256, 1) k_attn() {
  extern __shared__ __nv_bfloat16 smb[];
  int tid = threadIdx.x;
  int wid = tid >> 5, lane = tid & 31;
  int g = lane >> 2, t = lane & 3;
  int bh = blockIdx.y;
  int b = bh >> 3;
  int q0 = blockIdx.x * 128;
  int m0 = wid * 16;

  unsigned sb = (unsigned)__cvta_generic_to_shared(smb);

  // Q fragments (persistent): rows q0+m0+g, +8; 4 k-steps of 16
  unsigned qf[4][4];
  {
    const unsigned* qp0 = (const unsigned*)(g_qb + ((size_t)bh*L_ + q0 + m0 + g)*64);
    const unsigned* qp1 = qp0 + 8*32;
    #pragma unroll
    for (int ks = 0; ks < 4; ks++) {
      qf[ks][0] = qp0[8*ks + t];
      qf[ks][1] = qp1[8*ks + t];
      qf[ks][2] = qp0[8*ks + t + 4];
      qf[ks][3] = qp1[8*ks + t + 4];
    }
  }

  float oacc[16][4];
  #pragma unroll
  for (int j = 0; j < 16; j++)
    #pragma unroll
    for (int r = 0; r < 4; r++) oacc[j][r] = 0.f;
  float mrun0 = -1e30f, mrun1 = -1e30f, l0 = 0.f, l1 = 0.f;

  const float* snrl = g_snrlog + b*L_;
  const __nv_bfloat16* kbase = g_kb + (size_t)bh*L_*64;
  const __nv_bfloat16* vbase = g_vb + (size_t)bh*128*L_;

  // stage kt=0 into buffer 0
  {
    unsigned kS = sb;
    unsigned vS = sb + 9216*2;
    #pragma unroll
    for (int i = 0; i < 2; i++) {
      int idx = tid + 256*i; int row = idx >> 3, seg = idx & 7;
      cp16(kS + (unsigned)(row*72 + seg*8)*2, kbase + row*64 + seg*8);
    }
    #pragma unroll
    for (int i = 0; i < 4; i++) {
      int idx = tid + 256*i; int row = idx >> 3, seg = idx & 7;
      cp16(vS + (unsigned)(row*72 + seg*8)*2, vbase + (size_t)row*L_ + seg*8);
    }
  }
  asm volatile("cp.async.commit_group;");

  int stage = 0;
  for (int kt = 0; kt < 36; kt++) {
    if (kt + 1 < 36) {
      int kv1 = (kt + 1) * 64;
      int st = stage ^ 1;
      unsigned kS = sb + (unsigned)(st*KU)*2;
      unsigned vS = sb + (unsigned)(9216 + st*VU)*2;
      const __nv_bfloat16* kp = kbase + (size_t)kv1*64;
      const __nv_bfloat16* vp = vbase + kv1;
      #pragma unroll
      for (int i = 0; i < 2; i++) {
        int idx = tid + 256*i; int row = idx >> 3, seg = idx & 7;
        cp16(kS + (unsigned)(row*72 + seg*8)*2, kp + row*64 + seg*8);
      }
      #pragma unroll
      for (int i = 0; i < 4; i++) {
        int idx = tid + 256*i; int row = idx >> 3, seg = idx & 7;
        cp16(vS + (unsigned)(row*72 + seg*8)*2, vp + (size_t)row*L_ + seg*8);
      }
    }
    asm volatile("cp.async.commit_group;");
    asm volatile("cp.async.wait_group 1;");
    __syncthreads();

    const unsigned* sK32 = (const unsigned*)(smb + stage*KU);
    const unsigned* sV32 = (const unsigned*)(smb + 9216 + stage*VU);
    int kv0 = kt * 64;

    // ---- S = Q K^T : 32 MMAs ----
    float sacc[8][4];
    #pragma unroll
    for (int j = 0; j < 8; j++)
      #pragma unroll
      for (int r = 0; r < 4; r++) sacc[j][r] = 0.f;
    #pragma unroll
    for (int ks = 0; ks < 4; ks++) {
      #pragma unroll
      for (int j = 0; j < 8; j++) {
        int rbase = (8*j + g)*36 + 8*ks + t;
        unsigned b0 = sK32[rbase];
        unsigned b1 = sK32[rbase + 4];
        mma_bf16(sacc[j], qf[ks], b0, b1);
      }
    }

    // ---- scale + snr bias ----
    #pragma unroll
    for (int j = 0; j < 8; j++) {
      float2 sbv = *(const float2*)&snrl[kv0 + 8*j + 2*t];
      sacc[j][0] = sacc[j][0]*0.125f + sbv.x;
      sacc[j][1] = sacc[j][1]*0.125f + sbv.y;
      sacc[j][2] = sacc[j][2]*0.125f + sbv.x;
      sacc[j][3] = sacc[j][3]*0.125f + sbv.y;
    }

    // ---- online softmax (rows g, g+8) ----
    float m0l = -1e30f, m1l = -1e30f;
    #pragma unroll
    for (int j = 0; j < 8; j++) {
      m0l = fmaxf(m0l, fmaxf(sacc[j][0], sacc[j][1]));
      m1l = fmaxf(m1l, fmaxf(sacc[j][2], sacc[j][3]));
    }
    m0l = fmaxf(m0l, __shfl_xor_sync(0xffffffffu, m0l, 1));
    m0l = fmaxf(m0l, __shfl_xor_sync(0xffffffffu, m0l, 2));
    m1l = fmaxf(m1l, __shfl_xor_sync(0xffffffffu, m1l, 1));
    m1l = fmaxf(m1l, __shfl_xor_sync(0xffffffffu, m1l, 2));
    float m0n = fmaxf(mrun0, m0l), m1n = fmaxf(mrun1, m1l);
    float sc0 = __expf(mrun0 - m0n), sc1 = __expf(mrun1 - m1n);
    float s0 = 0.f, s1 = 0.f;
    #pragma unroll
    for (int j = 0; j < 8; j++) {
      float p0 = __expf(sacc[j][0] - m0n);
      float p1 = __expf(sacc[j][1] - m0n);
      float p2 = __expf(sacc[j][2] - m1n);
      float p3 = __expf(sacc[j][3] - m1n);
      sacc[j][0] = p0; sacc[j][1] = p1; sacc[j][2] = p2; sacc[j][3] = p3;
      s0 += p0 + p1; s1 += p2 + p3;
    }
    s0 += __shfl_xor_sync(0xffffffffu, s0, 1);
    s0 += __shfl_xor_sync(0xffffffffu, s0, 2);
    s1 += __shfl_xor_sync(0xffffffffu, s1, 1);
    s1 += __shfl_xor_sync(0xffffffffu, s1, 2);
    l0 = l0*sc0 + s0; l1 = l1*sc1 + s1;
    mrun0 = m0n; mrun1 = m1n;
    #pragma unroll
    for (int j = 0; j < 16; j++) {
      oacc[j][0] *= sc0; oacc[j][1] *= sc0;
      oacc[j][2] *= sc1; oacc[j][3] *= sc1;
    }

    // ---- O += P V : C-frag of S == A-frag of PV (no shuffles) ----
    #pragma unroll
    for (int js = 0; js < 4; js++) {
      unsigned pa[4];
      pa[0] = pk(sacc[2*js][0],   sacc[2*js][1]);
      pa[1] = pk(sacc[2*js][2],   sacc[2*js][3]);
      pa[2] = pk(sacc[2*js+1][0], sacc[2*js+1][1]);
      pa[3] = pk(sacc[2*js+1][2], sacc[2*js+1][3]);
      #pragma unroll
      for (int j2 = 0; j2 < 16; j2++) {
        int nb = (8*j2 + g)*36 + 8*js + t;
        unsigned b0 = sV32[nb];
        unsigned b1 = sV32[nb + 4];
        mma_bf16(oacc[j2], pa, b0, b1);
      }
    }
    stage ^= 1;
    __syncthreads();
  }

  float inv0 = 1.f / l0, inv1 = 1.f / l1;
  int h = bh & 7;
  int row0 = q0 + m0 + g;
  float* op0 = g_attno + ((size_t)(b*L_ + row0))*1024 + h*128;
  float* op1 = op0 + (size_t)8*1024;
  #pragma unroll
  for (int j2 = 0; j2 < 16; j2++) {
    float2 v0 = { oacc[j2][0]*inv0, oacc[j2][1]*inv0 };
    float2 v1 = { oacc[j2][2]*inv1, oacc[j2][3]*inv1 };
    *(float2*)&op0[8*j2 + 2*t] = v0;
    *(float2*)&op1[8*j2 + 2*t] = v1;
  }
}

// ---------------- K3: attn out proj + residual + LN ------------------------
__global__ void __launch_bounds__(128) k_attn_epi(const float* __restrict__ x,
                           const float* __restrict__ fc,
                           const float* __restrict__ lnw,
                           const float* __restrict__ lnb) {
  extern __shared__ float smep[];
  float* sA  = smep;                 // 16 x 1028
  float* sB0 = smep + 16*1028;       // 64 x 68
  float* sB1 = sB0 + 64*68;
  __shared__ float sout[16][64];
  int blk = blockIdx.x;
  int b = blk / 144;
  int t0 = (blk % 144) * 16;
  int tid = threadIdx.x;
  unsigned sbase = (unsigned)__cvta_generic_to_shared(smep);
  unsigned bbase[2] = { sbase + 16*1028*4, sbase + (16*1028 + 64*68)*4 };

  for (int i = tid*4; i < 16384; i += 512) {
    int tok = i >> 10, k = i & 1023;
    cp16(sbase + (unsigned)(tok*1028 + k)*4,
         &g_attno[((size_t)(b*L_ + t0 + tok))*1024 + k]);
  }
  for (int i = tid*4; i < 4096; i += 512) {
    int kk = i >> 6, c = i & 63;
    cp16(bbase[0] + (unsigned)(kk*68 + c)*4, &fc[(size_t)kk*64 + c]);
  }
  asm volatile("cp.async.commit_group;");

  int cg = tid & 15, tg = tid >> 4;
  float acc[2][4];
  #pragma unroll
  for (int u = 0; u < 2; u++)
    #pragma unroll
    for (int r = 0; r < 4; r++) acc[u][r] = 0.f;

  int buf = 0;
  for (int kc = 0; kc < 16; kc++) {
    if (kc + 1 < 16) {
      for (int i = tid*4; i < 4096; i += 512) {
        int kk = i >> 6, c = i & 63;
        cp16(bbase[buf ^ 1] + (unsigned)(kk*68 + c)*4,
             &fc[(size_t)((kc + 1)*64 + kk)*64 + c]);
      }
      asm volatile("cp.async.commit_group;");
      asm volatile("cp.async.wait_group 1;");
    } else {
      asm volatile("cp.async.wait_group 0;");
    }
    __syncthreads();
    const float* sB = buf ? sB1 : sB0;
    int kb = kc*64;
    #pragma unroll 4
    for (int kk = 0; kk < 64; kk++) {
      float4 w = *(const float4*)&sB[kk*68 + cg*4];
      float x0 = sA[(tg*2)*1028 + kb + kk];
      float x1 = sA[(tg*2 + 1)*1028 + kb + kk];
      acc[0][0] = fmaf(x0, w.x, acc[0][0]); acc[0][1] = fmaf(x0, w.y, acc[0][1]);
      acc[0][2] = fmaf(x0, w.z, acc[0][2]); acc[0][3] = fmaf(x0, w.w, acc[0][3]);
      acc[1][0] = fmaf(x1, w.x, acc[1][0]); acc[1][1] = fmaf(x1, w.y, acc[1][1]);
      acc[1][2] = fmaf(x1, w.z, acc[1][2]); acc[1][3] = fmaf(x1, w.w, acc[1][3]);
    }
    buf ^= 1;
    __syncthreads();
  }
  #pragma unroll
  for (int u = 0; u < 2; u++) {
    int tok = tg*2 + u;
    #pragma unroll
    for (int r = 0; r < 4; r++) {
      int c = cg*4 + r;
      sout[tok][c] = acc[u][r] + x[(b*C_ + c)*L_ + t0 + tok];
    }
  }
  __syncthreads();
  int lane = tid & 31, wid = tid >> 5;
  for (int tok = wid; tok < 16; tok += 4) {
    float v0 = sout[tok][lane], v1 = sout[tok][lane + 32];
    float mean = warp_sum(v0 + v1) * (1.f/64.f);
    float d0 = v0 - mean, d1 = v1 - mean;
    float var = warp_sum(d0*d0 + d1*d1) * (1.f/64.f);
    float rs = rsqrtf(var + 1e-5f);
    int l = t0 + tok;
    g_enc[(b*L_ + l)*64 + lane]      = d0*rs*lnw[lane] + lnb[lane];
    g_enc[(b*L_ + l)*64 + lane + 32] = d1*rs*lnw[lane + 32] + lnb[lane + 32];
  }
}

// ---------------- K4: SS input projection ----------------------------------
__global__ void k_ssin(const float* __restrict__ w) {
  extern __shared__ float sw[];
  __shared__ float sxe[16][64];
  int blk = blockIdx.x;
  int b = blk / (L_/16);
  int t0 = (blk % (L_/16)) * 16;
  int tid = threadIdx.x;
  for (int i = tid*4; i < 16384; i += 1024)
    *(float4*)&sw[i] = *(const float4*)&w[i];
  for (int i = tid; i < 1024; i += 256)
    sxe[i>>6][i&63] = g_enc[(b*L_ + t0 + (i>>6))*64 + (i&63)];
  __syncthreads();
  int tok = tid >> 4, c0 = tid & 15;
  float acc[16];
  #pragma unroll
  for (int j = 0; j < 16; j++) acc[j] = 0.f;
  for (int cc = 0; cc < 64; cc++) {
    float xv = sxe[tok][cc];
    #pragma unroll
    for (int j = 0; j < 16; j++) acc[j] = fmaf(xv, sw[cc*256 + c0 + 16*j], acc[j]);
  }
  int l = t0 + tok;
  #pragma unroll
  for (int j = 0; j < 16; j++) {
    int c = c0 + 16*j;
    if (c < 128) g_x1[(b*128 + c)*L_ + l] = acc[j];
    else         g_z[(b*L_ + l)*128 + (c - 128)] = acc[j];
  }
}

// ---------------- K5: depthwise conv3x3 + bias + silu ----------------------
__global__ void k_dw1(const float* __restrict__ w, const float* __restrict__ bias) {
  int p = blockIdx.x*256 + threadIdx.x;
  if (p >= B_*DN_*L_) return;
  int b = p / (DN_*L_);
  int rem = p - b*DN_*L_;
  int d = rem / L_;
  int hw = rem - d*L_;
  int i = hw / Ww, j = hw - i*Ww;
  const float* src = g_x1 + (b*DN_ + d)*L_;
  const float* wr = w + d*9;
  float acc = bias[d];
  #pragma unroll
  for (int kh = -1; kh <= 1; kh++) {
    int ih = i + kh;
    if (ih < 0 || ih >= Hh) continue;
    #pragma unroll
    for (int kw = -1; kw <= 1; kw++) {
      int iw = j + kw;
      if (iw < 0 || iw >= Ww) continue;
      acc = fmaf(src[ih*Ww + iw], wr[(kh+1)*3 + (kw+1)], acc);
    }
  }
  float s = acc / (1.f + __expf(-acc));
  g_x1c[(b*DN_ + d)*L_ + hw] = s;
}

__device__ __forceinline__ int xs_src(int k, int l) {
  if (k == 0) return l;
  int i = l / 48, j = l - i*48;
  if (k == 1) return j*48 + i;
  if (k == 2) return L_ - 1 - l;
  return (47 - j)*48 + (47 - i);
}

// ---------------- K6: x_dbl projection + dt proj + softplus ----------------
__global__ void k_xdbl(const float* __restrict__ xw,
                       const float* __restrict__ dtw,
                       const float* __restrict__ dtb) {
  __shared__ float sxs[16][130];
  __shared__ float sxw[128][37];
  __shared__ float sdt[16][4];
  __shared__ float sdtw[128][5];
  __shared__ float sdtbv[128];
  int t = blockIdx.x;
  int lt = t % 144;
  int k = (t / 144) & 3;
  int b = t / 576;
  int l0 = lt * 16;
  int tid = threadIdx.x;
  for (int i = tid; i < 4608; i += 256) {
    int c = i >> 7, d = i & 127;
    sxw[d][c] = xw[(size_t)k*4608 + i];
  }
  for (int i = tid; i < 512; i += 256) {
    int d = i >> 2, r = i & 3;
    sdtw[d][r] = dtw[(size_t)k*512 + i];
  }
  if (tid < 128) sdtbv[tid] = dtb[k*128 + tid];
  for (int i3 = tid; i3 < 2048; i3 += 256) {
    int tt = i3 >> 7, d = i3 & 127;
    int src = xs_src(k, l0 + tt);
    sxs[tt][d] = g_x1c[(b*128 + d)*L_ + src];
  }
  __syncthreads();
  for (int o = tid; o < 16*36; o += 256) {
    int ll = o / 36, c = o - ll*36;
    float acc = 0.f;
    #pragma unroll 4
    for (int d = 0; d < 128; d++) acc = fmaf(sxs[ll][d], sxw[d][c], acc);
    int l = l0 + ll;
    if (c < 4)       sdt[ll][c] = acc;
    else if (c < 20) g_Bs[((b*4 + k)*L_ + l)*16 + (c - 4)]  = acc;
    else             g_Cs[((b*4 + k)*L_ + l)*16 + (c - 20)] = acc;
  }
  __syncthreads();
  for (int o = tid; o < 16*128; o += 256) {
    int ll = o >> 7, d = o & 127;
    float acc = sdtbv[d];
    #pragma unroll
    for (int r = 0; r < 4; r++) acc = fmaf(sdt[ll][r], sdtw[d][r], acc);
    float sp = (acc > 20.f) ? acc : log1pf(__expf(acc));
    g_dts[((b*4 + k)*L_ + l0 + ll)*128 + d] = sp;
  }
}

// ---------------- K7: selective scan ---------------------------------------
__global__ void k_scan(const float* __restrict__ Alog, const float* __restrict__ Dw) {
  int gw = blockIdx.x;
  int lane = threadIdx.x;
  int b = gw >> 8;
  int rem = gw & 255;
  int k = rem >> 6;
  int dp = rem & 63;
  int n = lane & 15;
  int d = dp*2 + (lane >> 4);

  float An = -__expf(Alog[(k*128 + d)*16 + n]);
  float Dd = Dw[k*128 + d];
  const float* dtp = g_dts + ((size_t)(b*4 + k)*L_)*128 + d;
  const float* Bp  = g_Bs  + ((size_t)(b*4 + k)*L_)*16 + n;
  const float* Cp  = g_Cs  + ((size_t)(b*4 + k)*L_)*16 + n;
  float*       yp  = g_ys  + ((size_t)(b*4 + k)*L_)*128 + d;
  const float* xp  = g_x1c + (b*128 + d)*L_;

  float hst = 0.f;
  int ii = 0, jj = 0;
  for (int l0 = 0; l0 < L_; l0 += 8) {
    float dt[8], xv[8], Bn[8], Cn[8];
    #pragma unroll
    for (int u = 0; u < 8; u++) {
      int l = l0 + u;
      int src;
      if (k == 0)      src = l;
      else if (k == 1) src = jj*48 + ii;
      else if (k == 2) src = L_ - 1 - l;
      else             src = (47 - jj)*48 + (47 - ii);
      dt[u] = dtp[l*128];
      xv[u] = xp[src];
      Bn[u] = Bp[l*16];
      Cn[u] = Cp[l*16];
      jj++;
      if (jj == 48) { jj = 0; ii++; }
    }
    #pragma unroll
    for (int u = 0; u < 8; u++) {
      float dA = __expf(dt[u] * An);
      hst = fmaf(hst, dA, dt[u]*xv[u]*Bn[u]);
      float y = hst * Cn[u];
      y += __shfl_xor_sync(0xffffffffu, y, 1);
      y += __shfl_xor_sync(0xffffffffu, y, 2);
      y += __shfl_xor_sync(0xffffffffu, y, 4);
      y += __shfl_xor_sync(0xffffffffu, y, 8);
      if (n == 0) yp[(l0 + u)*128] = fmaf(Dd, xv[u], y);
    }
  }
}

// ---------------- K8: merge + LN + gate + out proj + LN --------------------
__global__ void __launch_bounds__(128) k_merge(const float* __restrict__ x,
                        const float* __restrict__ snr,
                        const float* __restrict__ nw, const float* __restrict__ nb,
                        const float* __restrict__ ow,
                        const float* __restrict__ flnw, const float* __restrict__ flnb) {
  __shared__ float sow[128*64];
  __shared__ float sy[128];
  __shared__ float red[4], red2[4];
  __shared__ float spart[2][64];
  int blk = blockIdx.x;
  int b = blk / 288;
  int t0 = (blk % 288) * 8;
  int tid = threadIdx.x, lane = tid & 31, wid = tid >> 5;
  for (int i = tid*4; i < 8192; i += 512)
    *(float4*)&sow[i] = *(const float4*)&ow[i];
  size_t base = (size_t)b*4*L_*128;
  float nwv = nw[tid], nbv = nb[tid];
  __syncthreads();

  for (int tok = 0; tok < 8; tok++) {
    int l = t0 + tok;
    int i = l / 48, j = l - i*48;
    int lt = j*48 + i;
    float y = g_ys[base + ((size_t)0*L_ + l)*128 + tid]
            + g_ys[base + ((size_t)2*L_ + (L_ - 1 - l))*128 + tid]
            + g_ys[base + ((size_t)1*L_ + lt)*128 + tid]
            + g_ys[base + ((size_t)3*L_ + (L_ - 1 - lt))*128 + tid];
    float s1 = warp_sum(y), s2 = warp_sum(y*y);
    if (lane == 0) { red[wid] = s1; red2[wid] = s2; }
    __syncthreads();
    float mean = (red[0] + red[1] + red[2] + red[3]) * (1.f/128.f);
    float var  = fmaxf((red2[0] + red2[1] + red2[2] + red2[3]) * (1.f/128.f) - mean*mean, 0.f);
    float yn = (y - mean) * rsqrtf(var + 1e-5f) * nwv + nbv;
    float z = g_z[(b*L_ + l)*128 + tid];
    float sz = z / (1.f + __expf(-z));
    float sv = snr[b*L_ + l];
    sy[tid] = yn * sz * sv;
    __syncthreads();
    {
      int c = tid & 63, half = tid >> 6;
      float acc = 0.f;
      int d0 = half*64;
      #pragma unroll 8
      for (int d = 0; d < 64; d++) acc = fmaf(sy[d0 + d], sow[(d0 + d)*64 + c], acc);
      spart[half][c] = acc;
    }
    __syncthreads();
    float v = 0.f;
    if (tid < 64) {
      v = spart[0][tid] + spart[1][tid] + x[(b*C_ + tid)*L_ + l];
      g_x2[(b*L_ + l)*64 + tid] = v;
    }
    float t1 = warp_sum(tid < 64 ? v : 0.f);
    float t2 = warp_sum(tid < 64 ? v*v : 0.f);
    if (lane == 0) { red[wid] = t1; red2[wid] = t2; }
    __syncthreads();
    float mean2 = (red[0] + red[1]) * (1.f/64.f);
    float var2  = fmaxf((red2[0] + red2[1]) * (1.f/64.f) - mean2*mean2, 0.f);
    if (tid < 64)
      g_xn[(b*L_ + l)*64 + tid] = (v - mean2) * rsqrtf(var2 + 1e-5f) * flnw[tid] + flnb[tid];
    __syncthreads();
  }
}

// ---------------- K9: FFN conv1x1 64->256 + gelu ---------------------------
__global__ void k_ffn1(const float* __restrict__ w1) {
  extern __shared__ float sw1[];
  __shared__ float sx[16][64];
  int blk = blockIdx.x;
  int b = blk / (L_/16);
  int t0 = (blk % (L_/16)) * 16;
  int tid = threadIdx.x;
  for (int i = tid; i < 16384; i += 256) {
    int oc = i >> 6, cc = i & 63;
    sw1[cc*257 + oc] = w1[i];
  }
  for (int i = tid; i < 1024; i += 256) {
    int tt = i >> 6, cc = i & 63;
    sx[tt][cc] = g_xn[(b*L_ + t0 + tt)*64 + cc];
  }
  __syncthreads();
  int oc = tid;
  float acc[16];
  #pragma unroll
  for (int q = 0; q < 16; q++) acc[q] = 0.f;
  for (int cc = 0; cc < 64; cc++) {
    float w = sw1[cc*257 + oc];
    #pragma unroll
    for (int q = 0; q < 16; q++) acc[q] = fmaf(sx[q][cc], w, acc[q]);
  }
  float* dst = g_h1 + (b*CM_ + oc)*L_ + t0;
  #pragma unroll
  for (int q = 0; q < 16; q++) dst[q] = gelu_exact(acc[q]);
}

// ---------------- K10: FFN depthwise conv3x3 + gelu ------------------------
__global__ void k_dw2(const float* __restrict__ w) {
  int p = blockIdx.x*256 + threadIdx.x;
  if (p >= B_*CM_*L_) return;
  int b = p / (CM_*L_);
  int rem = p - b*CM_*L_;
  int ch = rem / L_;
  int hw = rem - ch*L_;
  int i = hw / Ww, j = hw - i*Ww;
  const float* src = g_h1 + (b*CM_ + ch)*L_;
  const float* wr = w + ch*9;
  float acc = 0.f;
  #pragma unroll
  for (int kh = -1; kh <= 1; kh++) {
    int ih = i + kh;
    if (ih < 0 || ih >= Hh) continue;
    #pragma unroll
    for (int kw = -1; kw <= 1; kw++) {
      int iw = j + kw;
      if (iw < 0 || iw >= Ww) continue;
      acc = fmaf(src[ih*Ww + iw], wr[(kh+1)*3 + (kw+1)], acc);
    }
  }
  g_h2[(b*CM_ + ch)*L_ + hw] = gelu_exact(acc);
}

// ---------------- K11: FFN conv1x1 256->64 + residual ----------------------
__global__ void k_ffn2(const float* __restrict__ w2, float* __restrict__ out) {
  extern __shared__ float sw2[];
  __shared__ float sh[256][16];
  int blk = blockIdx.x;
  int b = blk / (L_/16);
  int t0 = (blk % (L_/16)) * 16;
  int tid = threadIdx.x;
  for (int i = tid; i < 16384; i += 256) {
    int c = i >> 8, oc = i & 255;
    sw2[oc*65 + c] = w2[i];
  }
  for (int i = tid; i < 4096; i += 256) {
    int oc = i >> 4, tt = i & 15;
    sh[oc][tt] = g_h2[(b*CM_ + oc)*L_ + t0 + tt];
  }
  __syncthreads();
  int c = tid & 63, tg = tid >> 6;
  float acc[4] = {0.f, 0.f, 0.f, 0.f};
  for (int oc = 0; oc < 256; oc++) {
    float w = sw2[oc*65 + c];
    #pragma unroll
    for (int q = 0; q < 4; q++) acc[q] = fmaf(sh[oc][tg + 4*q], w, acc[q]);
  }
  #pragma unroll
  for (int q = 0; q < 4; q++) {
    int l = t0 + tg + 4*q;
    out[(b*C_ + c)*L_ + l] = acc[q] + g_x2[(b*L_ + l)*64 + c];
  }
}

// ---------------- launch ----------------------------------------------------
extern "C" void kernel_launch(void* const* d_in, const int* in_sizes, int n_in,
                              void* d_out, int out_size) {
  const float* enc     = (const float*)d_in[0];
  const float* snr     = (const float*)d_in[1];
  const float* wq      = (const float*)d_in[2];
  const float* wk      = (const float*)d_in[3];
  const float* wv      = (const float*)d_in[4];
  const float* fc      = (const float*)d_in[5];
  const float* aln_w   = (const float*)d_in[6];
  const float* aln_b   = (const float*)d_in[7];
  const float* ss_in_w = (const float*)d_in[8];
  const float* conv_w  = (const float*)d_in[9];
  const float* conv_b  = (const float*)d_in[10];
  const float* xproj   = (const float*)d_in[11];
  const float* dtw     = (const float*)d_in[12];
  const float* dtb     = (const float*)d_in[13];
  const float* Alog    = (const float*)d_in[14];
  const float* Dw      = (const float*)d_in[15];
  const float* norm_w  = (const float*)d_in[16];
  const float* norm_b  = (const float*)d_in[17];
  const float* out_w   = (const float*)d_in[18];
  const float* flnw    = (const float*)d_in[19];
  const float* flnb    = (const float*)d_in[20];
  const float* w1      = (const float*)d_in[21];
  const float* dw      = (const float*)d_in[22];
  const float* w2      = (const float*)d_in[23];
  float* out = (float*)d_out;

  const int attn_smem = (2*KU + 2*VU) * 2;                    // 55296 B
  const int epi_smem  = (16*1028 + 2*64*68) * 4;              // 100608 B
  const int ffn1_smem = 64*257*4;
  const int ffn2_smem = 256*65*4;
  cudaFuncSetAttribute(k_attn, cudaFuncAttributeMaxDynamicSharedMemorySize, attn_smem);
  cudaFuncSetAttribute(k_attn_epi, cudaFuncAttributeMaxDynamicSharedMemorySize, epi_smem);
  cudaFuncSetAttribute(k_ssin, cudaFuncAttributeMaxDynamicSharedMemorySize, 65536);
  cudaFuncSetAttribute(k_ffn1, cudaFuncAttributeMaxDynamicSharedMemorySize, ffn1_smem);
  cudaFuncSetAttribute(k_ffn2, cudaFuncAttributeMaxDynamicSharedMemorySize, ffn2_smem);

  k_qkv<<<576, 256>>>(enc, wq, wk, wv, snr);
  k_attn<<<dim3(18, 16), 256, attn_smem>>>();
  k_attn_epi<<<288, 128, epi_smem>>>(enc, fc, aln_w, aln_b);
  k_ssin<<<288, 256, 65536>>>(ss_in_w);
  k_dw1<<<(B_*DN_*L_ + 255)/256, 256>>>(conv_w, conv_b);
  k_xdbl<<<1152, 256>>>(xproj, dtw, dtb);
  k_scan<<<512, 32>>>(Alog, Dw);
  k_merge<<<576, 128>>>(enc, snr, norm_w, norm_b, out_w, flnw, flnb);
  k_ffn1<<<288, 256, ffn1_smem>>>(w1);
  k_dw2<<<(B_*CM_*L_ + 255)/256, 256>>>(dw);
  k_ffn2<<<288, 256, ffn2_smem>>>(w2, out);
}

// round 14
// speedup vs baseline: 1.4008x; 1.0268x over previous
#include <cuda_runtime.h>
#include <cuda_bf16.h>
#include <math.h>

constexpr int B_ = 2, C_ = 64, Hh = 48, Ww = 48, L_ = 2304;
constexpr int NH_ = 8, DK_ = 64, DV_ = 128;
constexpr int DN_ = 128, NS_ = 16, CM_ = 256;

// ---------------- scratch ---------------------------------------------------
__device__ __nv_bfloat16 g_qb[B_*NH_*L_*DK_];    // [bh][l][64]
__device__ __nv_bfloat16 g_kb[B_*NH_*L_*DK_];    // [bh][l][64]
__device__ __nv_bfloat16 g_vb[B_*NH_*DV_*L_];    // [bh][d][L]  (transposed)
__device__ float g_snrlog[B_*L_];
__device__ float g_attno[B_*L_*NH_*DV_];
__device__ float g_enc[B_*L_*C_];
__device__ float g_z[B_*L_*DN_];
__device__ float g_x1[B_*DN_*L_];
__device__ float g_x1c[B_*DN_*L_];
__device__ float g_dts[B_*4*L_*DN_];
__device__ float g_Bs[B_*4*L_*NS_];
__device__ float g_Cs[B_*4*L_*NS_];
__device__ float g_ys[B_*4*L_*DN_];
__device__ float g_x2[B_*L_*C_];
__device__ float g_xn[B_*L_*C_];
__device__ float g_h1[B_*CM_*L_];
__device__ float g_h2[B_*CM_*L_];

__device__ __forceinline__ float warp_sum(float v) {
  #pragma unroll
  for (int o = 16; o > 0; o >>= 1) v += __shfl_xor_sync(0xffffffffu, v, o);
  return v;
}

__device__ __forceinline__ float gelu_exact(float x) {
  return 0.5f * x * (1.0f + erff(x * 0.70710678118654752f));
}

// pack (lo, hi) floats -> bf16x2 (lo at lower address)
__device__ __forceinline__ unsigned pk(float lo, float hi) {
  unsigned r;
  asm("cvt.rn.bf16x2.f32 %0, %1, %2;" : "=r"(r) : "f"(hi), "f"(lo));
  return r;
}

__device__ __forceinline__ void mma_bf16(float* d, const unsigned* a, unsigned b0, unsigned b1) {
  asm volatile("mma.sync.aligned.m16n8k16.row.col.f32.bf16.bf16.f32 "
    "{%0,%1,%2,%3}, {%4,%5,%6,%7}, {%8,%9}, {%0,%1,%2,%3};"
    : "+f"(d[0]), "+f"(d[1]), "+f"(d[2]), "+f"(d[3])
    : "r"(a[0]), "r"(a[1]), "r"(a[2]), "r"(a[3]), "r"(b0), "r"(b1));
}

__device__ __forceinline__ void cp16(unsigned s, const void* g) {
  asm volatile("cp.async.cg.shared.global [%0], [%1], 16;" :: "r"(s), "l"(g));
}

// ---------------- K0: snr log ------------------------------------------------
__global__ void k_snr(const float* __restrict__ snr) {
  int i = blockIdx.x*512 + threadIdx.x;
  if (i < B_*L_) g_snrlog[i] = logf(snr[i] + 1e-4f);
}

// ---------------- K1: QKV projection via bf16 tensor MMA --------------------
// grid (72 token-tiles of 64, 8 col-tiles of 256), block 256.
// ct 0-1: Q, 2-3: K (A = x tokens, B = w cols); ct 4-7: V (A = w cols, B = x).
__global__ void __launch_bounds__(256) k_qkv(const float* __restrict__ x,
                      const float* __restrict__ wq,
                      const float* __restrict__ wk,
                      const float* __restrict__ wv) {
  __shared__ __nv_bfloat16 swx[256*66];     // stride 66 bf16 = 33 words: conflict-free
  int b = blockIdx.x / 36;
  int t0 = (blockIdx.x % 36) * 64;
  int ct = blockIdx.y;
  int tid = threadIdx.x;
  int wid = tid >> 5, lane = tid & 31;
  int g = lane >> 2, t = lane & 3;
  const float* xb = x + (size_t)b*C_*L_;

  if (ct < 4) {
    // ---------------- Q/K block ----------------
    const float* wbase = (ct < 2) ? wq : wk;
    int cb = (ct & 1) * 256;
    // stage w slice [64 cc][256 col] -> swx[col][cc]
    for (int i = tid; i < 16384; i += 256) {
      int cc = i >> 8, col = i & 255;
      swx[col*66 + cc] = __float2bfloat16(wbase[cc*512 + cb + col]);
    }
    __syncthreads();
    int l0 = t0 + (wid & 3)*16;
    int half = wid >> 2;
    // A fragments from global x (rows = tokens, k = cc)
    unsigned a[4][4];
    #pragma unroll
    for (int ks = 0; ks < 4; ks++) {
      int k0 = 16*ks + 2*t;
      a[ks][0] = pk(xb[k0*L_ + l0+g],       xb[(k0+1)*L_ + l0+g]);
      a[ks][1] = pk(xb[k0*L_ + l0+g+8],     xb[(k0+1)*L_ + l0+g+8]);
      a[ks][2] = pk(xb[(k0+8)*L_ + l0+g],   xb[(k0+9)*L_ + l0+g]);
      a[ks][3] = pk(xb[(k0+8)*L_ + l0+g+8], xb[(k0+9)*L_ + l0+g+8]);
    }
    float acc[16][4];
    #pragma unroll
    for (int j = 0; j < 16; j++)
      #pragma unroll
      for (int r = 0; r < 4; r++) acc[j][r] = 0.f;
    const unsigned* sw32 = (const unsigned*)swx;
    #pragma unroll
    for (int j = 0; j < 16; j++) {
      int n = half*128 + 8*j + g;
      #pragma unroll
      for (int ks = 0; ks < 4; ks++) {
        unsigned b0 = sw32[n*33 + 8*ks + t];
        unsigned b1 = sw32[n*33 + 8*ks + t + 4];
        mma_bf16(acc[j], a[ks], b0, b1);
      }
    }
    __nv_bfloat16* dst = (ct < 2) ? g_qb : g_kb;
    #pragma unroll
    for (int j = 0; j < 16; j++) {
      int gcol = cb + half*128 + 8*j + 2*t;
      int h = gcol >> 6, d = gcol & 63;
      *(unsigned*)&dst[((size_t)(b*8 + h)*L_ + l0 + g)*64 + d]     = pk(acc[j][0], acc[j][1]);
      *(unsigned*)&dst[((size_t)(b*8 + h)*L_ + l0 + g + 8)*64 + d] = pk(acc[j][2], acc[j][3]);
    }
  } else {
    // ---------------- V block: C[d][token] ----------------
    int cbv = (ct - 4) * 256;
    // stage x tile [64 tok][64 cc] -> swx[tok][cc]
    for (int i = tid; i < 4096; i += 256) {
      int tt = i & 63, cc = i >> 6;
      swx[tt*66 + cc] = __float2bfloat16(xb[cc*L_ + t0 + tt]);
    }
    __syncthreads();
    int d0 = wid * 32;
    unsigned a[2][4][4];
    #pragma unroll
    for (int mi = 0; mi < 2; mi++) {
      int gv = cbv + d0 + mi*16;
      #pragma unroll
      for (int ks = 0; ks < 4; ks++) {
        int k0 = 16*ks + 2*t;
        a[mi][ks][0] = pk(wv[(size_t)k0*1024 + gv+g],       wv[(size_t)(k0+1)*1024 + gv+g]);
        a[mi][ks][1] = pk(wv[(size_t)k0*1024 + gv+g+8],     wv[(size_t)(k0+1)*1024 + gv+g+8]);
        a[mi][ks][2] = pk(wv[(size_t)(k0+8)*1024 + gv+g],   wv[(size_t)(k0+9)*1024 + gv+g]);
        a[mi][ks][3] = pk(wv[(size_t)(k0+8)*1024 + gv+g+8], wv[(size_t)(k0+9)*1024 + gv+g+8]);
      }
    }
    float acc[2][8][4];
    #pragma unroll
    for (int mi = 0; mi < 2; mi++)
      #pragma unroll
      for (int j = 0; j < 8; j++)
        #pragma unroll
        for (int r = 0; r < 4; r++) acc[mi][j][r] = 0.f;
    const unsigned* sx32 = (const unsigned*)swx;
    #pragma unroll
    for (int j = 0; j < 8; j++) {
      int n = 8*j + g;
      #pragma unroll
      for (int ks = 0; ks < 4; ks++) {
        unsigned b0 = sx32[n*33 + 8*ks + t];
        unsigned b1 = sx32[n*33 + 8*ks + t + 4];
        #pragma unroll
        for (int mi = 0; mi < 2; mi++)
          mma_bf16(acc[mi][j], a[mi][ks], b0, b1);
      }
    }
    #pragma unroll
    for (int mi = 0; mi < 2; mi++) {
      int gdr = cbv + d0 + mi*16 + g;
      int h = gdr >> 7, dl = gdr & 127;
      #pragma unroll
      for (int j = 0; j < 8; j++) {
        int l = t0 + 8*j + 2*t;
        *(unsigned*)&g_vb[((size_t)(b*8 + h)*128 + dl)*L_ + l]     = pk(acc[mi][j][0], acc[mi][j][1]);
        *(unsigned*)&g_vb[((size_t)(b*8 + h)*128 + dl + 8)*L_ + l] = pk(acc[mi][j][2], acc[mi][j][3]);
      }
    }
  }
}

// ---------------- K2: flash attention, bf16 m16n8k16 -----------------------
constexpr int KU = 4608;      // 64*72
constexpr int VU = 9216;      // 128*72

__global__ void __launch_bounds__(256, 1) k_attn() {
  extern __shared__ __nv_bfloat16 smb[];
  int tid = threadIdx.x;
  int wid = tid >> 5, lane = tid & 31;
  int g = lane >> 2, t = lane & 3;
  int bh = blockIdx.y;
  int b = bh >> 3;
  int q0 = blockIdx.x * 128;
  int m0 = wid * 16;

  unsigned sb = (unsigned)__cvta_generic_to_shared(smb);

  unsigned qf[4][4];
  {
    const unsigned* qp0 = (const unsigned*)(g_qb + ((size_t)bh*L_ + q0 + m0 + g)*64);
    const unsigned* qp1 = qp0 + 8*32;
    #pragma unroll
    for (int ks = 0; ks < 4; ks++) {
      qf[ks][0] = qp0[8*ks + t];
      qf[ks][1] = qp1[8*ks + t];
      qf[ks][2] = qp0[8*ks + t + 4];
      qf[ks][3] = qp1[8*ks + t + 4];
    }
  }

  float oacc[16][4];
  #pragma unroll
  for (int j = 0; j < 16; j++)
    #pragma unroll
    for (int r = 0; r < 4; r++) oacc[j][r] = 0.f;
  float mrun0 = -1e30f, mrun1 = -1e30f, l0 = 0.f, l1 = 0.f;

  const float* snrl = g_snrlog + b*L_;
  const __nv_bfloat16* kbase = g_kb + (size_t)bh*L_*64;
  const __nv_bfloat16* vbase = g_vb + (size_t)bh*128*L_;

  {
    unsigned kS = sb;
    unsigned vS = sb + 9216*2;
    #pragma unroll
    for (int i = 0; i < 2; i++) {
      int idx = tid + 256*i; int row = idx >> 3, seg = idx & 7;
      cp16(kS + (unsigned)(row*72 + seg*8)*2, kbase + row*64 + seg*8);
    }
    #pragma unroll
    for (int i = 0; i < 4; i++) {
      int idx = tid + 256*i; int row = idx >> 3, seg = idx & 7;
      cp16(vS + (unsigned)(row*72 + seg*8)*2, vbase + (size_t)row*L_ + seg*8);
    }
  }
  asm volatile("cp.async.commit_group;");

  int stage = 0;
  for (int kt = 0; kt < 36; kt++) {
    if (kt + 1 < 36) {
      int kv1 = (kt + 1) * 64;
      int st = stage ^ 1;
      unsigned kS = sb + (unsigned)(st*KU)*2;
      unsigned vS = sb + (unsigned)(9216 + st*VU)*2;
      const __nv_bfloat16* kp = kbase + (size_t)kv1*64;
      const __nv_bfloat16* vp = vbase + kv1;
      #pragma unroll
      for (int i = 0; i < 2; i++) {
        int idx = tid + 256*i; int row = idx >> 3, seg = idx & 7;
        cp16(kS + (unsigned)(row*72 + seg*8)*2, kp + row*64 + seg*8);
      }
      #pragma unroll
      for (int i = 0; i < 4; i++) {
        int idx = tid + 256*i; int row = idx >> 3, seg = idx & 7;
        cp16(vS + (unsigned)(row*72 + seg*8)*2, vp + (size_t)row*L_ + seg*8);
      }
    }
    asm volatile("cp.async.commit_group;");
    asm volatile("cp.async.wait_group 1;");
    __syncthreads();

    const unsigned* sK32 = (const unsigned*)(smb + stage*KU);
    const unsigned* sV32 = (const unsigned*)(smb + 9216 + stage*VU);
    int kv0 = kt * 64;

    float sacc[8][4];
    #pragma unroll
    for (int j = 0; j < 8; j++)
      #pragma unroll
      for (int r = 0; r < 4; r++) sacc[j][r] = 0.f;
    #pragma unroll
    for (int ks = 0; ks < 4; ks++) {
      #pragma unroll
      for (int j = 0; j < 8; j++) {
        int rbase = (8*j + g)*36 + 8*ks + t;
        unsigned b0 = sK32[rbase];
        unsigned b1 = sK32[rbase + 4];
        mma_bf16(sacc[j], qf[ks], b0, b1);
      }
    }

    #pragma unroll
    for (int j = 0; j < 8; j++) {
      float2 sbv = *(const float2*)&snrl[kv0 + 8*j + 2*t];
      sacc[j][0] = sacc[j][0]*0.125f + sbv.x;
      sacc[j][1] = sacc[j][1]*0.125f + sbv.y;
      sacc[j][2] = sacc[j][2]*0.125f + sbv.x;
      sacc[j][3] = sacc[j][3]*0.125f + sbv.y;
    }

    float m0l = -1e30f, m1l = -1e30f;
    #pragma unroll
    for (int j = 0; j < 8; j++) {
      m0l = fmaxf(m0l, fmaxf(sacc[j][0], sacc[j][1]));
      m1l = fmaxf(m1l, fmaxf(sacc[j][2], sacc[j][3]));
    }
    m0l = fmaxf(m0l, __shfl_xor_sync(0xffffffffu, m0l, 1));
    m0l = fmaxf(m0l, __shfl_xor_sync(0xffffffffu, m0l, 2));
    m1l = fmaxf(m1l, __shfl_xor_sync(0xffffffffu, m1l, 1));
    m1l = fmaxf(m1l, __shfl_xor_sync(0xffffffffu, m1l, 2));
    float m0n = fmaxf(mrun0, m0l), m1n = fmaxf(mrun1, m1l);
    float sc0 = __expf(mrun0 - m0n), sc1 = __expf(mrun1 - m1n);
    float s0 = 0.f, s1 = 0.f;
    #pragma unroll
    for (int j = 0; j < 8; j++) {
      float p0 = __expf(sacc[j][0] - m0n);
      float p1 = __expf(sacc[j][1] - m0n);
      float p2 = __expf(sacc[j][2] - m1n);
      float p3 = __expf(sacc[j][3] - m1n);
      sacc[j][0] = p0; sacc[j][1] = p1; sacc[j][2] = p2; sacc[j][3] = p3;
      s0 += p0 + p1; s1 += p2 + p3;
    }
    s0 += __shfl_xor_sync(0xffffffffu, s0, 1);
    s0 += __shfl_xor_sync(0xffffffffu, s0, 2);
    s1 += __shfl_xor_sync(0xffffffffu, s1, 1);
    s1 += __shfl_xor_sync(0xffffffffu, s1, 2);
    l0 = l0*sc0 + s0; l1 = l1*sc1 + s1;
    mrun0 = m0n; mrun1 = m1n;
    #pragma unroll
    for (int j = 0; j < 16; j++) {
      oacc[j][0] *= sc0; oacc[j][1] *= sc0;
      oacc[j][2] *= sc1; oacc[j][3] *= sc1;
    }

    #pragma unroll
    for (int js = 0; js < 4; js++) {
      unsigned pa[4];
      pa[0] = pk(sacc[2*js][0],   sacc[2*js][1]);
      pa[1] = pk(sacc[2*js][2],   sacc[2*js][3]);
      pa[2] = pk(sacc[2*js+1][0], sacc[2*js+1][1]);
      pa[3] = pk(sacc[2*js+1][2], sacc[2*js+1][3]);
      #pragma unroll
      for (int j2 = 0; j2 < 16; j2++) {
        int nb = (8*j2 + g)*36 + 8*js + t;
        unsigned b0 = sV32[nb];
        unsigned b1 = sV32[nb + 4];
        mma_bf16(oacc[j2], pa, b0, b1);
      }
    }
    stage ^= 1;
    __syncthreads();
  }

  float inv0 = 1.f / l0, inv1 = 1.f / l1;
  int h = bh & 7;
  int row0 = q0 + m0 + g;
  float* op0 = g_attno + ((size_t)(b*L_ + row0))*1024 + h*128;
  float* op1 = op0 + (size_t)8*1024;
  #pragma unroll
  for (int j2 = 0; j2 < 16; j2++) {
    float2 v0 = { oacc[j2][0]*inv0, oacc[j2][1]*inv0 };
    float2 v1 = { oacc[j2][2]*inv1, oacc[j2][3]*inv1 };
    *(float2*)&op0[8*j2 + 2*t] = v0;
    *(float2*)&op1[8*j2 + 2*t] = v1;
  }
}

// ---------------- K3: attn out proj + residual + LN ------------------------
__global__ void __launch_bounds__(128) k_attn_epi(const float* __restrict__ x,
                           const float* __restrict__ fc,
                           const float* __restrict__ lnw,
                           const float* __restrict__ lnb) {
  extern __shared__ float smep[];
  float* sB0 = smep + 16*1028;
  float* sB1 = sB0 + 64*68;
  __shared__ float sout[16][64];
  int blk = blockIdx.x;
  int b = blk / 144;
  int t0 = (blk % 144) * 16;
  int tid = threadIdx.x;
  float* sA = smep;
  unsigned sbase = (unsigned)__cvta_generic_to_shared(smep);
  unsigned bbase[2] = { sbase + 16*1028*4, sbase + (16*1028 + 64*68)*4 };

  for (int i = tid*4; i < 16384; i += 512) {
    int tok = i >> 10, k = i & 1023;
    cp16(sbase + (unsigned)(tok*1028 + k)*4,
         &g_attno[((size_t)(b*L_ + t0 + tok))*1024 + k]);
  }
  for (int i = tid*4; i < 4096; i += 512) {
    int kk = i >> 6, c = i & 63;
    cp16(bbase[0] + (unsigned)(kk*68 + c)*4, &fc[(size_t)kk*64 + c]);
  }
  asm volatile("cp.async.commit_group;");

  int cg = tid & 15, tg = tid >> 4;
  float acc[2][4];
  #pragma unroll
  for (int u = 0; u < 2; u++)
    #pragma unroll
    for (int r = 0; r < 4; r++) acc[u][r] = 0.f;

  int buf = 0;
  for (int kc = 0; kc < 16; kc++) {
    if (kc + 1 < 16) {
      for (int i = tid*4; i < 4096; i += 512) {
        int kk = i >> 6, c = i & 63;
        cp16(bbase[buf ^ 1] + (unsigned)(kk*68 + c)*4,
             &fc[(size_t)((kc + 1)*64 + kk)*64 + c]);
      }
      asm volatile("cp.async.commit_group;");
      asm volatile("cp.async.wait_group 1;");
    } else {
      asm volatile("cp.async.wait_group 0;");
    }
    __syncthreads();
    const float* sB = buf ? sB1 : sB0;
    int kb = kc*64;
    #pragma unroll 4
    for (int kk = 0; kk < 64; kk++) {
      float4 w = *(const float4*)&sB[kk*68 + cg*4];
      float x0 = sA[(tg*2)*1028 + kb + kk];
      float x1 = sA[(tg*2 + 1)*1028 + kb + kk];
      acc[0][0] = fmaf(x0, w.x, acc[0][0]); acc[0][1] = fmaf(x0, w.y, acc[0][1]);
      acc[0][2] = fmaf(x0, w.z, acc[0][2]); acc[0][3] = fmaf(x0, w.w, acc[0][3]);
      acc[1][0] = fmaf(x1, w.x, acc[1][0]); acc[1][1] = fmaf(x1, w.y, acc[1][1]);
      acc[1][2] = fmaf(x1, w.z, acc[1][2]); acc[1][3] = fmaf(x1, w.w, acc[1][3]);
    }
    buf ^= 1;
    __syncthreads();
  }
  #pragma unroll
  for (int u = 0; u < 2; u++) {
    int tok = tg*2 + u;
    #pragma unroll
    for (int r = 0; r < 4; r++) {
      int c = cg*4 + r;
      sout[tok][c] = acc[u][r] + x[(b*C_ + c)*L_ + t0 + tok];
    }
  }
  __syncthreads();
  int lane = tid & 31, wid = tid >> 5;
  for (int tok = wid; tok < 16; tok += 4) {
    float v0 = sout[tok][lane], v1 = sout[tok][lane + 32];
    float mean = warp_sum(v0 + v1) * (1.f/64.f);
    float d0 = v0 - mean, d1 = v1 - mean;
    float var = warp_sum(d0*d0 + d1*d1) * (1.f/64.f);
    float rs = rsqrtf(var + 1e-5f);
    int l = t0 + tok;
    g_enc[(b*L_ + l)*64 + lane]      = d0*rs*lnw[lane] + lnb[lane];
    g_enc[(b*L_ + l)*64 + lane + 32] = d1*rs*lnw[lane + 32] + lnb[lane + 32];
  }
}

// ---------------- K4: SS input projection (float4 smem reads) --------------
__global__ void k_ssin(const float* __restrict__ w) {
  extern __shared__ float sw[];
  __shared__ float sxe[16][64];
  int blk = blockIdx.x;
  int b = blk / 144;
  int t0 = (blk % 144) * 16;
  int tid = threadIdx.x;
  for (int i = tid*4; i < 16384; i += 1024)
    *(float4*)&sw[i] = *(const float4*)&w[i];
  for (int i = tid; i < 1024; i += 256)
    sxe[i>>6][i&63] = g_enc[(b*L_ + t0 + (i>>6))*64 + (i&63)];
  __syncthreads();
  int cg = tid & 63, tg = tid >> 6;
  float acc[4][4];
  #pragma unroll
  for (int u = 0; u < 4; u++)
    #pragma unroll
    for (int r = 0; r < 4; r++) acc[u][r] = 0.f;
  for (int cc = 0; cc < 64; cc++) {
    float4 w4 = *(const float4*)&sw[cc*256 + cg*4];
    #pragma unroll
    for (int u = 0; u < 4; u++) {
      float xv = sxe[tg*4 + u][cc];
      acc[u][0] = fmaf(xv, w4.x, acc[u][0]);
      acc[u][1] = fmaf(xv, w4.y, acc[u][1]);
      acc[u][2] = fmaf(xv, w4.z, acc[u][2]);
      acc[u][3] = fmaf(xv, w4.w, acc[u][3]);
    }
  }
  #pragma unroll
  for (int u = 0; u < 4; u++) {
    int l = t0 + tg*4 + u;
    if (cg < 32) {
      #pragma unroll
      for (int r = 0; r < 4; r++)
        g_x1[(b*128 + cg*4 + r)*L_ + l] = acc[u][r];
    } else {
      float4 v = { acc[u][0], acc[u][1], acc[u][2], acc[u][3] };
      *(float4*)&g_z[((size_t)b*L_ + l)*128 + (cg - 32)*4] = v;
    }
  }
}

// ---------------- K5: depthwise conv3x3 + bias + silu ----------------------
__global__ void k_dw1(const float* __restrict__ w, const float* __restrict__ bias) {
  int p = blockIdx.x*256 + threadIdx.x;
  if (p >= B_*DN_*L_) return;
  int b = p / (DN_*L_);
  int rem = p - b*DN_*L_;
  int d = rem / L_;
  int hw = rem - d*L_;
  int i = hw / Ww, j = hw - i*Ww;
  const float* src = g_x1 + (b*DN_ + d)*L_;
  const float* wr = w + d*9;
  float acc = bias[d];
  #pragma unroll
  for (int kh = -1; kh <= 1; kh++) {
    int ih = i + kh;
    if (ih < 0 || ih >= Hh) continue;
    #pragma unroll
    for (int kw = -1; kw <= 1; kw++) {
      int iw = j + kw;
      if (iw < 0 || iw >= Ww) continue;
      acc = fmaf(src[ih*Ww + iw], wr[(kh+1)*3 + (kw+1)], acc);
    }
  }
  float s = acc / (1.f + __expf(-acc));
  g_x1c[(b*DN_ + d)*L_ + hw] = s;
}

__device__ __forceinline__ int xs_src(int k, int l) {
  if (k == 0) return l;
  int i = l / 48, j = l - i*48;
  if (k == 1) return j*48 + i;
  if (k == 2) return L_ - 1 - l;
  return (47 - j)*48 + (47 - i);
}

// ---------------- K6: x_dbl projection + dt proj + softplus ----------------
__global__ void k_xdbl(const float* __restrict__ xw,
                       const float* __restrict__ dtw,
                       const float* __restrict__ dtb) {
  __shared__ float sxs[16][130];
  __shared__ float sxw[128][37];
  __shared__ float sdt[16][4];
  __shared__ float sdtw[128][5];
  __shared__ float sdtbv[128];
  int t = blockIdx.x;
  int lt = t % 144;
  int k = (t / 144) & 3;
  int b = t / 576;
  int l0 = lt * 16;
  int tid = threadIdx.x;
  for (int i = tid; i < 4608; i += 256) {
    int c = i >> 7, d = i & 127;
    sxw[d][c] = xw[(size_t)k*4608 + i];
  }
  for (int i = tid; i < 512; i += 256) {
    int d = i >> 2, r = i & 3;
    sdtw[d][r] = dtw[(size_t)k*512 + i];
  }
  if (tid < 128) sdtbv[tid] = dtb[k*128 + tid];
  for (int i3 = tid; i3 < 2048; i3 += 256) {
    int tt = i3 >> 7, d = i3 & 127;
    int src = xs_src(k, l0 + tt);
    sxs[tt][d] = g_x1c[(b*128 + d)*L_ + src];
  }
  __syncthreads();
  for (int o = tid; o < 16*36; o += 256) {
    int ll = o / 36, c = o - ll*36;
    float acc = 0.f;
    #pragma unroll 4
    for (int d = 0; d < 128; d++) acc = fmaf(sxs[ll][d], sxw[d][c], acc);
    int l = l0 + ll;
    if (c < 4)       sdt[ll][c] = acc;
    else if (c < 20) g_Bs[((b*4 + k)*L_ + l)*16 + (c - 4)]  = acc;
    else             g_Cs[((b*4 + k)*L_ + l)*16 + (c - 20)] = acc;
  }
  __syncthreads();
  for (int o = tid; o < 16*128; o += 256) {
    int ll = o >> 7, d = o & 127;
    float acc = sdtbv[d];
    #pragma unroll
    for (int r = 0; r < 4; r++) acc = fmaf(sdt[ll][r], sdtw[d][r], acc);
    float sp = (acc > 20.f) ? acc : log1pf(__expf(acc));
    g_dts[((b*4 + k)*L_ + l0 + ll)*128 + d] = sp;
  }
}

// ---------------- K7: selective scan ---------------------------------------
__global__ void k_scan(const float* __restrict__ Alog, const float* __restrict__ Dw) {
  int gw = blockIdx.x;
  int lane = threadIdx.x;
  int b = gw >> 8;
  int rem = gw & 255;
  int k = rem >> 6;
  int dp = rem & 63;
  int n = lane & 15;
  int d = dp*2 + (lane >> 4);

  float An = -__expf(Alog[(k*128 + d)*16 + n]);
  float Dd = Dw[k*128 + d];
  const float* dtp = g_dts + ((size_t)(b*4 + k)*L_)*128 + d;
  const float* Bp  = g_Bs  + ((size_t)(b*4 + k)*L_)*16 + n;
  const float* Cp  = g_Cs  + ((size_t)(b*4 + k)*L_)*16 + n;
  float*       yp  = g_ys  + ((size_t)(b*4 + k)*L_)*128 + d;
  const float* xp  = g_x1c + (b*128 + d)*L_;

  float hst = 0.f;
  int ii = 0, jj = 0;
  for (int l0 = 0; l0 < L_; l0 += 8) {
    float dt[8], xv[8], Bn[8], Cn[8];
    #pragma unroll
    for (int u = 0; u < 8; u++) {
      int l = l0 + u;
      int src;
      if (k == 0)      src = l;
      else if (k == 1) src = jj*48 + ii;
      else if (k == 2) src = L_ - 1 - l;
      else             src = (47 - jj)*48 + (47 - ii);
      dt[u] = dtp[l*128];
      xv[u] = xp[src];
      Bn[u] = Bp[l*16];
      Cn[u] = Cp[l*16];
      jj++;
      if (jj == 48) { jj = 0; ii++; }
    }
    #pragma unroll
    for (int u = 0; u < 8; u++) {
      float dA = __expf(dt[u] * An);
      hst = fmaf(hst, dA, dt[u]*xv[u]*Bn[u]);
      float y = hst * Cn[u];
      y += __shfl_xor_sync(0xffffffffu, y, 1);
      y += __shfl_xor_sync(0xffffffffu, y, 2);
      y += __shfl_xor_sync(0xffffffffu, y, 4);
      y += __shfl_xor_sync(0xffffffffu, y, 8);
      if (n == 0) yp[(l0 + u)*128] = fmaf(Dd, xv[u], y);
    }
  }
}

// ---------------- K8: merge + LN + gate + out proj + LN (2 tokens/iter) ----
__global__ void __launch_bounds__(256) k_merge(const float* __restrict__ x,
                        const float* __restrict__ snr,
                        const float* __restrict__ nw, const float* __restrict__ nb,
                        const float* __restrict__ ow,
                        const float* __restrict__ flnw, const float* __restrict__ flnb) {
  __shared__ float sow[128*64];
  __shared__ float sy[2][128];
  __shared__ float red[2][4], red2[2][4];
  __shared__ float spart[2][2][64];
  int blk = blockIdx.x;
  int b = blk / 288;
  int t0 = (blk % 288) * 8;
  int tid = threadIdx.x;
  int th = tid & 127, half = tid >> 7;
  int lane = th & 31, w4 = th >> 5;
  for (int i = tid*4; i < 8192; i += 1024)
    *(float4*)&sow[i] = *(const float4*)&ow[i];
  size_t base = (size_t)b*4*L_*128;
  float nwv = nw[th], nbv = nb[th];
  __syncthreads();

  for (int it = 0; it < 4; it++) {
    int l = t0 + it*2 + half;
    int i = l / 48, j = l - i*48;
    int lt = j*48 + i;
    float y = g_ys[base + ((size_t)0*L_ + l)*128 + th]
            + g_ys[base + ((size_t)2*L_ + (L_ - 1 - l))*128 + th]
            + g_ys[base + ((size_t)1*L_ + lt)*128 + th]
            + g_ys[base + ((size_t)3*L_ + (L_ - 1 - lt))*128 + th];
    float s1 = warp_sum(y), s2 = warp_sum(y*y);
    if (lane == 0) { red[half][w4] = s1; red2[half][w4] = s2; }
    __syncthreads();
    float mean = (red[half][0] + red[half][1] + red[half][2] + red[half][3]) * (1.f/128.f);
    float var  = fmaxf((red2[half][0] + red2[half][1] + red2[half][2] + red2[half][3]) * (1.f/128.f) - mean*mean, 0.f);
    float yn = (y - mean) * rsqrtf(var + 1e-5f) * nwv + nbv;
    float z = g_z[(b*L_ + l)*128 + th];
    float sz = z / (1.f + __expf(-z));
    float sv = snr[b*L_ + l];
    sy[half][th] = yn * sz * sv;
    __syncthreads();
    {
      int c = th & 63, hh = th >> 6;
      float acc = 0.f;
      int d0 = hh*64;
      #pragma unroll 8
      for (int d = 0; d < 64; d++) acc = fmaf(sy[half][d0 + d], sow[(d0 + d)*64 + c], acc);
      spart[half][hh][c] = acc;
    }
    __syncthreads();
    float v = 0.f;
    if (th < 64) {
      v = spart[half][0][th] + spart[half][1][th] + x[(b*C_ + th)*L_ + l];
      g_x2[(b*L_ + l)*64 + th] = v;
    }
    float t1 = warp_sum(th < 64 ? v : 0.f);
    float t2 = warp_sum(th < 64 ? v*v : 0.f);
    if (lane == 0) { red[half][w4] = t1; red2[half][w4] = t2; }
    __syncthreads();
    float mean2 = (red[half][0] + red[half][1]) * (1.f/64.f);
    float var2  = fmaxf((red2[half][0] + red2[half][1]) * (1.f/64.f) - mean2*mean2, 0.f);
    if (th < 64)
      g_xn[(b*L_ + l)*64 + th] = (v - mean2) * rsqrtf(var2 + 1e-5f) * flnw[th] + flnb[th];
    __syncthreads();
  }
}

// ---------------- K9: FFN conv1x1 64->256 + gelu ---------------------------
__global__ void k_ffn1(const float* __restrict__ w1) {
  extern __shared__ float sw1[];
  __shared__ float sx[16][64];
  int blk = blockIdx.x;
  int b = blk / 144;
  int t0 = (blk % 144) * 16;
  int tid = threadIdx.x;
  for (int i = tid; i < 16384; i += 256) {
    int oc = i >> 6, cc = i & 63;
    sw1[cc*257 + oc] = w1[i];
  }
  for (int i = tid; i < 1024; i += 256) {
    int tt = i >> 6, cc = i & 63;
    sx[tt][cc] = g_xn[(b*L_ + t0 + tt)*64 + cc];
  }
  __syncthreads();
  int oc = tid;
  float acc[16];
  #pragma unroll
  for (int q = 0; q < 16; q++) acc[q] = 0.f;
  for (int cc = 0; cc < 64; cc++) {
    float w = sw1[cc*257 + oc];
    #pragma unroll
    for (int q = 0; q < 16; q++) acc[q] = fmaf(sx[q][cc], w, acc[q]);
  }
  float* dst = g_h1 + (b*CM_ + oc)*L_ + t0;
  #pragma unroll
  for (int q = 0; q < 16; q++) dst[q] = gelu_exact(acc[q]);
}

// ---------------- K10: FFN depthwise conv3x3 + gelu ------------------------
__global__ void k_dw2(const float* __restrict__ w) {
  int p = blockIdx.x*256 + threadIdx.x;
  if (p >= B_*CM_*L_) return;
  int b = p / (CM_*L_);
  int rem = p - b*CM_*L_;
  int ch = rem / L_;
  int hw = rem - ch*L_;
  int i = hw / Ww, j = hw - i*Ww;
  const float* src = g_h1 + (b*CM_ + ch)*L_;
  const float* wr = w + ch*9;
  float acc = 0.f;
  #pragma unroll
  for (int kh = -1; kh <= 1; kh++) {
    int ih = i + kh;
    if (ih < 0 || ih >= Hh) continue;
    #pragma unroll
    for (int kw = -1; kw <= 1; kw++) {
      int iw = j + kw;
      if (iw < 0 || iw >= Ww) continue;
      acc = fmaf(src[ih*Ww + iw], wr[(kh+1)*3 + (kw+1)], acc);
    }
  }
  g_h2[(b*CM_ + ch)*L_ + hw] = gelu_exact(acc);
}

// ---------------- K11: FFN conv1x1 256->64 + residual ----------------------
__global__ void k_ffn2(const float* __restrict__ w2, float* __restrict__ out) {
  extern __shared__ float sw2[];
  __shared__ float sh[256][16];
  int blk = blockIdx.x;
  int b = blk / 144;
  int t0 = (blk % 144) * 16;
  int tid = threadIdx.x;
  for (int i = tid; i < 16384; i += 256) {
    int c = i >> 8, oc = i & 255;
    sw2[oc*65 + c] = w2[i];
  }
  for (int i = tid; i < 4096; i += 256) {
    int oc = i >> 4, tt = i & 15;
    sh[oc][tt] = g_h2[(b*CM_ + oc)*L_ + t0 + tt];
  }
  __syncthreads();
  int c = tid & 63, tg = tid >> 6;
  float acc[4] = {0.f, 0.f, 0.f, 0.f};
  for (int oc = 0; oc < 256; oc++) {
    float w = sw2[oc*65 + c];
    #pragma unroll
    for (int q = 0; q < 4; q++) acc[q] = fmaf(sh[oc][tg + 4*q], w, acc[q]);
  }
  #pragma unroll
  for (int q = 0; q < 4; q++) {
    int l = t0 + tg + 4*q;
    out[(b*C_ + c)*L_ + l] = acc[q] + g_x2[(b*L_ + l)*64 + c];
  }
}

// ---------------- launch ----------------------------------------------------
extern "C" void kernel_launch(void* const* d_in, const int* in_sizes, int n_in,
                              void* d_out, int out_size) {
  const float* enc     = (const float*)d_in[0];
  const float* snr     = (const float*)d_in[1];
  const float* wq      = (const float*)d_in[2];
  const float* wk      = (const float*)d_in[3];
  const float* wv      = (const float*)d_in[4];
  const float* fc      = (const float*)d_in[5];
  const float* aln_w   = (const float*)d_in[6];
  const float* aln_b   = (const float*)d_in[7];
  const float* ss_in_w = (const float*)d_in[8];
  const float* conv_w  = (const float*)d_in[9];
  const float* conv_b  = (const float*)d_in[10];
  const float* xproj   = (const float*)d_in[11];
  const float* dtw     = (const float*)d_in[12];
  const float* dtb     = (const float*)d_in[13];
  const float* Alog    = (const float*)d_in[14];
  const float* Dw      = (const float*)d_in[15];
  const float* norm_w  = (const float*)d_in[16];
  const float* norm_b  = (const float*)d_in[17];
  const float* out_w   = (const float*)d_in[18];
  const float* flnw    = (const float*)d_in[19];
  const float* flnb    = (const float*)d_in[20];
  const float* w1      = (const float*)d_in[21];
  const float* dw      = (const float*)d_in[22];
  const float* w2      = (const float*)d_in[23];
  float* out = (float*)d_out;

  const int attn_smem = (2*KU + 2*VU) * 2;                    // 55296 B
  const int epi_smem  = (16*1028 + 2*64*68) * 4;              // 100608 B
  const int ffn1_smem = 64*257*4;
  const int ffn2_smem = 256*65*4;
  cudaFuncSetAttribute(k_attn, cudaFuncAttributeMaxDynamicSharedMemorySize, attn_smem);
  cudaFuncSetAttribute(k_attn_epi, cudaFuncAttributeMaxDynamicSharedMemorySize, epi_smem);
  cudaFuncSetAttribute(k_ssin, cudaFuncAttributeMaxDynamicSharedMemorySize, 65536);
  cudaFuncSetAttribute(k_ffn1, cudaFuncAttributeMaxDynamicSharedMemorySize, ffn1_smem);
  cudaFuncSetAttribute(k_ffn2, cudaFuncAttributeMaxDynamicSharedMemorySize, ffn2_smem);

  k_snr<<<9, 512>>>(snr);
  k_qkv<<<dim3(72, 8), 256>>>(enc, wq, wk, wv);
  k_attn<<<dim3(18, 16), 256, attn_smem>>>();
  k_attn_epi<<<288, 128, epi_smem>>>(enc, fc, aln_w, aln_b);
  k_ssin<<<288, 256, 65536>>>(ss_in_w);
  k_dw1<<<(B_*DN_*L_ + 255)/256, 256>>>(conv_w, conv_b);
  k_xdbl<<<1152, 256>>>(xproj, dtw, dtb);
  k_scan<<<512, 32>>>(Alog, Dw);
  k_merge<<<576, 256>>>(enc, snr, norm_w, norm_b, out_w, flnw, flnb);
  k_ffn1<<<288, 256, ffn1_smem>>>(w1);
  k_dw2<<<(B_*CM_*L_ + 255)/256, 256>>>(dw);
  k_ffn2<<<288, 256, ffn2_smem>>>(w2, out);
}